// round 14
// baseline (speedup 1.0000x reference)
#include <cuda_runtime.h>
#include <cuda_bf16.h>
#include <math.h>
#include <stdint.h>

#define NLAYER 4
#define D 1024
#define H 16
#define KVH 4
#define HD 64
#define NE 8
#define KTOP 2
#define FF 512
#define VOCAB 32000
#define BB 2
#define TT 1024
#define NTASK 10
#define NEVAL 5
#define NTOK (BB*TT)
#define EPSV 1e-6f
#define REP (H/KVH)
#define QKVW (H*HD + 2*KVH*HD)   // 1536

#define TM 128
#define TN 128

#define QT 64
#define APAD 68
#define ATTN_SMEM (3*64*APAD*4)

// ---------------- scratch (device globals; no allocations) ----------------
__device__ float g_x[NTOK*D];
__device__ float g_norm[NTOK*D];
__device__ uint32_t g_norm_hi[NTOK*(D/2)];
__device__ uint32_t g_norm_lo[NTOK*(D/2)];
__device__ float g_qkv[NTOK*QKVW];
__device__ float g_wqkv[NLAYER*D*QKVW];
__device__ uint32_t g_att_hi[NTOK*(D/2)];
__device__ uint32_t g_att_lo[NTOK*(D/2)];
__device__ float g_hg[NE*NTOK*FF];
__device__ float g_hu[NE*NTOK*FF];
__device__ uint32_t g_hs_hi[NE*NTOK*(FF/2)];
__device__ uint32_t g_hs_lo[NE*NTOK*(FF/2)];

__device__ float g_probs[NTOK*NE];
__device__ float g_gfull[NTOK*NE];
__device__ int   g_cnt[NE];
__device__ int   g_list[NE*NTOK];
__device__ float g_aux[1];
__device__ float g_xmean[BB*D];

// ---------------- helpers ----------------
__device__ __forceinline__ uint32_t packbf(float lo_v, float hi_v) {
    uint32_t r;
    asm("cvt.rn.bf16x2.f32 %0, %1, %2;" : "=r"(r) : "f"(hi_v), "f"(lo_v));
    return r;
}

__device__ __forceinline__ void split2(float x, float y, uint32_t& hi, uint32_t& lo) {
    hi = packbf(x, y);
    __nv_bfloat162 h2 = *reinterpret_cast<__nv_bfloat162*>(&hi);
    float rx = x - __bfloat162float(h2.x);
    float ry = y - __bfloat162float(h2.y);
    lo = packbf(rx, ry);
}

__device__ __forceinline__ void mma_bf16(float (&c)[4], uint32_t a0, uint32_t a1,
                                         uint32_t a2, uint32_t a3, uint32_t b0, uint32_t b1) {
    asm volatile(
        "mma.sync.aligned.m16n8k16.row.col.f32.bf16.bf16.f32 "
        "{%0,%1,%2,%3}, {%4,%5,%6,%7}, {%8,%9}, {%0,%1,%2,%3};"
        : "+f"(c[0]), "+f"(c[1]), "+f"(c[2]), "+f"(c[3])
        : "r"(a0), "r"(a1), "r"(a2), "r"(a3), "r"(b0), "r"(b1));
}

__device__ __forceinline__ float siluf(float g) { return g / (1.f + expf(-g)); }

// single-buffer smem (R6 layout)
#define GEMM_SMEM_DECL                                \
    __shared__ uint32_t Ahi[8][TM + 8];               \
    __shared__ uint32_t Alo[8][TM + 8];               \
    __shared__ uint32_t Bhi[8][TN + 8];               \
    __shared__ uint32_t Blo[8][TN + 8];

// A-side: pre-split hi/lo words stored directly (no converts)
#define STORE_A_PRE(pah, pal, arow, akp)                                      \
    do {                                                                       \
        _Pragma("unroll") for (int i = 0; i < 2; i++) {                        \
            int r = (arow) + i * 64;                                           \
            Ahi[akp][r] = pah[i].x; Ahi[(akp) + 1][r] = pah[i].y;              \
            Alo[akp][r] = pal[i].x; Alo[(akp) + 1][r] = pal[i].y;              \
        }                                                                      \
    } while (0)

// B-side: fp32 k-pair rows, split in-loop (R6 pattern)
#define STORE_B_SPLIT(pb0, pb1, kp, ncol)                                     \
    do {                                                                       \
        split2(pb0.x, pb1.x, Bhi[kp][(ncol) + 0], Blo[kp][(ncol) + 0]);        \
        split2(pb0.y, pb1.y, Bhi[kp][(ncol) + 1], Blo[kp][(ncol) + 1]);        \
        split2(pb0.z, pb1.z, Bhi[kp][(ncol) + 2], Blo[kp][(ncol) + 2]);        \
        split2(pb0.w, pb1.w, Bhi[kp][(ncol) + 3], Blo[kp][(ncol) + 3]);        \
    } while (0)

// one 16-k step of 3-product bf16 emulated-fp32 mma
#define MMA_STEP16(mb, nb, lane, c)                                           \
    do {                                                                       \
        int kq = (lane) & 3;                                                   \
        int mrw = (lane) >> 2;                                                 \
        uint32_t ah[4][4], al[4][4], bh[4][2], bl[4][2];                       \
        _Pragma("unroll") for (int mt = 0; mt < 4; mt++) {                     \
            int m = (mb) + mt * 16 + mrw;                                      \
            ah[mt][0] = Ahi[kq][m];     ah[mt][1] = Ahi[kq][m + 8];            \
            ah[mt][2] = Ahi[kq + 4][m]; ah[mt][3] = Ahi[kq + 4][m + 8];        \
            al[mt][0] = Alo[kq][m];     al[mt][1] = Alo[kq][m + 8];            \
            al[mt][2] = Alo[kq + 4][m]; al[mt][3] = Alo[kq + 4][m + 8];        \
        }                                                                      \
        _Pragma("unroll") for (int nt = 0; nt < 4; nt++) {                     \
            int n = (nb) + nt * 8 + mrw;                                       \
            bh[nt][0] = Bhi[kq][n]; bh[nt][1] = Bhi[kq + 4][n];                \
            bl[nt][0] = Blo[kq][n]; bl[nt][1] = Blo[kq + 4][n];                \
        }                                                                      \
        _Pragma("unroll") for (int mt = 0; mt < 4; mt++)                       \
            _Pragma("unroll") for (int nt = 0; nt < 4; nt++) {                 \
                mma_bf16(c[mt][nt], ah[mt][0], ah[mt][1], ah[mt][2],           \
                         ah[mt][3], bl[nt][0], bl[nt][1]);                     \
                mma_bf16(c[mt][nt], al[mt][0], al[mt][1], al[mt][2],           \
                         al[mt][3], bh[nt][0], bh[nt][1]);                     \
                mma_bf16(c[mt][nt], ah[mt][0], ah[mt][1], ah[mt][2],           \
                         ah[mt][3], bh[nt][0], bh[nt][1]);                     \
            }                                                                  \
    } while (0)

// ---------------- embedding gather ----------------
__global__ void embed_kernel(const int* __restrict__ ids, const float* __restrict__ ew) {
    int n = blockIdx.x;
    int id = ids[n];
    const float* src = ew + (size_t)id * D;
    float* dst = g_x + (size_t)n * D;
    for (int d = threadIdx.x; d < D; d += blockDim.x) dst[d] = src[d];
}

// ---------------- rmsnorm (fp32 out + hi/lo split out) ----------------
__global__ void rmsnorm_kernel(const float* __restrict__ x, const float* __restrict__ w,
                               float* __restrict__ out) {
    int n = blockIdx.x;
    const float* xr = x + (size_t)n * D;
    float s = 0.f;
    for (int d = threadIdx.x; d < D; d += blockDim.x) { float v = xr[d]; s += v * v; }
    for (int o = 16; o; o >>= 1) s += __shfl_xor_sync(0xffffffffu, s, o);
    __shared__ float rb[8];
    if ((threadIdx.x & 31) == 0) rb[threadIdx.x >> 5] = s;
    __syncthreads();
    __shared__ float srms;
    if (threadIdx.x == 0) {
        float t = 0.f;
        for (int i = 0; i < 8; i++) t += rb[i];
        srms = rsqrtf(t / D + EPSV);
    }
    __syncthreads();
    float rms = srms;
    float* o2 = out + (size_t)n * D;
    uint32_t* ohi = g_norm_hi + (size_t)n * (D / 2);
    uint32_t* olo = g_norm_lo + (size_t)n * (D / 2);
    for (int p = threadIdx.x; p < D / 2; p += blockDim.x) {
        float v0 = w[2 * p] * xr[2 * p] * rms;
        float v1 = w[2 * p + 1] * xr[2 * p + 1] * rms;
        o2[2 * p] = v0;
        o2[2 * p + 1] = v1;
        uint32_t h, l;
        split2(v0, v1, h, l);
        ohi[p] = h;
        olo[p] = l;
    }
}

// ======== bf16x3 GEMM: pre-split A, fp32 B (in-loop split), single buffer ========
// C[M,N] (+)= A[M,K] @ B[K,N].  grid: (x = M-blocks, y = N-blocks).  K%16==0, N%128==0.
__global__ __launch_bounds__(256) void gemm_bf16(
    const uint32_t* __restrict__ Ah_g, const uint32_t* __restrict__ Al_g,
    const float* __restrict__ B, float* __restrict__ C,
    int M, int N, int K, int accum) {
    GEMM_SMEM_DECL
    int tid = threadIdx.x;
    int row0 = blockIdx.x * TM;
    int col0 = blockIdx.y * TN;
    if (row0 >= M) return;
    int lane = tid & 31, w = tid >> 5;
    int mb = (w & 1) * 64, nb = (w >> 1) * 32;
    int arow = tid >> 2, akp = (tid & 3) << 1;
    int kpB = tid >> 5, ncol = (tid & 31) << 2;
    int KP = K >> 1;

    const uint32_t *Ahp[2], *Alp[2];
#pragma unroll
    for (int i = 0; i < 2; i++) {
        int r = row0 + arow + i * 64;
        int rc = (r < M) ? r : (M - 1);
        Ahp[i] = Ah_g + (size_t)rc * KP + akp;
        Alp[i] = Al_g + (size_t)rc * KP + akp;
    }
    const float* Bp0 = B + (size_t)(2 * kpB) * N + col0 + ncol;
    const float* Bp1 = Bp0 + N;

    uint2 pah[2], pal[2];
    float4 pb0, pb1;
#pragma unroll
    for (int i = 0; i < 2; i++) {
        pah[i] = *(const uint2*)(Ahp[i]);
        pal[i] = *(const uint2*)(Alp[i]);
    }
    pb0 = *(const float4*)(Bp0);
    pb1 = *(const float4*)(Bp1);

    float c[4][4][4] = {};
    for (int k0 = 0; k0 < KP; k0 += 8) {     // k0 in k-pair units; 8 pairs = 16 k
        STORE_A_PRE(pah, pal, arow, akp);
        STORE_B_SPLIT(pb0, pb1, kpB, ncol);
        __syncthreads();
        if (k0 + 8 < KP) {
#pragma unroll
            for (int i = 0; i < 2; i++) {
                pah[i] = *(const uint2*)(Ahp[i] + k0 + 8);
                pal[i] = *(const uint2*)(Alp[i] + k0 + 8);
            }
            pb0 = *(const float4*)(Bp0 + (size_t)(2 * (k0 + 8)) * N);
            pb1 = *(const float4*)(Bp1 + (size_t)(2 * (k0 + 8)) * N);
        }
        MMA_STEP16(mb, nb, lane, c);
        __syncthreads();
    }
#pragma unroll
    for (int mt = 0; mt < 4; mt++) {
        int rt = row0 + mb + mt * 16 + (lane >> 2);
#pragma unroll
        for (int nt = 0; nt < 4; nt++) {
            int cc = col0 + nb + nt * 8 + ((lane & 3) << 1);
            if (rt < M) {
                float2* p = (float2*)&C[(size_t)rt * N + cc];
                float2 v = make_float2(c[mt][nt][0], c[mt][nt][1]);
                if (accum) { float2 o = *p; v.x += o.x; v.y += o.y; }
                *p = v;
            }
            if (rt + 8 < M) {
                float2* p = (float2*)&C[(size_t)(rt + 8) * N + cc];
                float2 v = make_float2(c[mt][nt][2], c[mt][nt][3]);
                if (accum) { float2 o = *p; v.x += o.x; v.y += o.y; }
                *p = v;
            }
        }
    }
}

static inline void gemm(const uint32_t* Ah, const uint32_t* Al, const float* B, float* C,
                        int M, int N, int K, int accum = 0) {
    dim3 grid((M + TM - 1) / TM, N / TN);
    gemm_bf16<<<grid, 256>>>(Ah, Al, B, C, M, N, K, accum);
}

// ========== MoE up/gate GEMM (gathered pre-split A, fp32 weights) ==========
__global__ __launch_bounds__(256) void moe_up_gemm(
    const float* __restrict__ Wg, const float* __restrict__ Wu) {
    int z = blockIdx.z;
    int e = z >> 1, u = z & 1;
    int cnt = g_cnt[e];
    int row0 = blockIdx.x * TM;
    if (row0 >= cnt) return;
    GEMM_SMEM_DECL
    int tid = threadIdx.x;
    int col0 = blockIdx.y * TN;
    int lane = tid & 31, w = tid >> 5;
    int mb = (w & 1) * 64, nb = (w >> 1) * 32;
    int arow = tid >> 2, akp = (tid & 3) << 1;
    int kpB = tid >> 5, ncol = (tid & 31) << 2;
    const int* list = g_list + e * NTOK;
    const int KP = D / 2;
    const float* B = (u ? Wu : Wg) + (size_t)e * D * FF;
    float* C = (u ? g_hu : g_hg) + (size_t)e * NTOK * FF;

    const uint32_t *Ahp[2], *Alp[2];
#pragma unroll
    for (int i = 0; i < 2; i++) {
        int r = row0 + arow + i * 64;
        int rc = (r < cnt) ? r : (cnt - 1);
        int tok = list[rc];
        Ahp[i] = g_norm_hi + (size_t)tok * KP + akp;
        Alp[i] = g_norm_lo + (size_t)tok * KP + akp;
    }
    const float* Bp0 = B + (size_t)(2 * kpB) * FF + col0 + ncol;
    const float* Bp1 = Bp0 + FF;

    uint2 pah[2], pal[2];
    float4 pb0, pb1;
#pragma unroll
    for (int i = 0; i < 2; i++) {
        pah[i] = *(const uint2*)(Ahp[i]);
        pal[i] = *(const uint2*)(Alp[i]);
    }
    pb0 = *(const float4*)(Bp0);
    pb1 = *(const float4*)(Bp1);

    float c[4][4][4] = {};
    for (int k0 = 0; k0 < KP; k0 += 8) {
        STORE_A_PRE(pah, pal, arow, akp);
        STORE_B_SPLIT(pb0, pb1, kpB, ncol);
        __syncthreads();
        if (k0 + 8 < KP) {
#pragma unroll
            for (int i = 0; i < 2; i++) {
                pah[i] = *(const uint2*)(Ahp[i] + k0 + 8);
                pal[i] = *(const uint2*)(Alp[i] + k0 + 8);
            }
            pb0 = *(const float4*)(Bp0 + (size_t)(2 * (k0 + 8)) * FF);
            pb1 = *(const float4*)(Bp1 + (size_t)(2 * (k0 + 8)) * FF);
        }
        MMA_STEP16(mb, nb, lane, c);
        __syncthreads();
    }
#pragma unroll
    for (int mt = 0; mt < 4; mt++) {
        int rt = row0 + mb + mt * 16 + (lane >> 2);
#pragma unroll
        for (int nt = 0; nt < 4; nt++) {
            int cc = col0 + nb + nt * 8 + ((lane & 3) << 1);
            if (rt < cnt)
                *(float2*)&C[(size_t)rt * FF + cc] = make_float2(c[mt][nt][0], c[mt][nt][1]);
            if (rt + 8 < cnt)
                *(float2*)&C[(size_t)(rt + 8) * FF + cc] = make_float2(c[mt][nt][2], c[mt][nt][3]);
        }
    }
}

// ---------------- silu-mul + split pre-pass for down GEMM A ----------------
__global__ void silu_split_kernel() {
    int e = blockIdx.y;
    int idx = blockIdx.x * blockDim.x + threadIdx.x;
    int r = idx >> 8;          // FF/2 = 256
    int kp = idx & 255;
    if (r >= g_cnt[e]) return;
    size_t base = (size_t)e * NTOK * FF + (size_t)r * FF + 2 * kp;
    float2 g2 = *(const float2*)&g_hg[base];
    float2 u2 = *(const float2*)&g_hu[base];
    float v0 = siluf(g2.x) * u2.x;
    float v1 = siluf(g2.y) * u2.y;
    uint32_t h, l;
    split2(v0, v1, h, l);
    size_t o = (size_t)e * NTOK * (FF / 2) + (size_t)r * (FF / 2) + kp;
    g_hs_hi[o] = h;
    g_hs_lo[o] = l;
}

// ========== MoE down GEMM (pre-split A, fp32 Wd, gated scatter-add) ==========
__global__ __launch_bounds__(256) void moe_down_gemm(const float* __restrict__ Wd) {
    int e = blockIdx.z;
    int cnt = g_cnt[e];
    int row0 = blockIdx.x * TM;
    if (row0 >= cnt) return;
    GEMM_SMEM_DECL
    int tid = threadIdx.x;
    int col0 = blockIdx.y * TN;
    int lane = tid & 31, w = tid >> 5;
    int mb = (w & 1) * 64, nb = (w >> 1) * 32;
    int arow = tid >> 2, akp = (tid & 3) << 1;
    int kpB = tid >> 5, ncol = (tid & 31) << 2;
    const int* list = g_list + e * NTOK;
    const int KP = FF / 2;
    const float* B = Wd + (size_t)e * FF * D;

    const uint32_t *Ahp[2], *Alp[2];
#pragma unroll
    for (int i = 0; i < 2; i++) {
        int r = row0 + arow + i * 64;
        int rc = (r < cnt) ? r : (cnt - 1);
        size_t base = (size_t)e * NTOK * KP + (size_t)rc * KP + akp;
        Ahp[i] = g_hs_hi + base;
        Alp[i] = g_hs_lo + base;
    }
    const float* Bp0 = B + (size_t)(2 * kpB) * D + col0 + ncol;
    const float* Bp1 = Bp0 + D;

    uint2 pah[2], pal[2];
    float4 pb0, pb1;
#pragma unroll
    for (int i = 0; i < 2; i++) {
        pah[i] = *(const uint2*)(Ahp[i]);
        pal[i] = *(const uint2*)(Alp[i]);
    }
    pb0 = *(const float4*)(Bp0);
    pb1 = *(const float4*)(Bp1);

    float c[4][4][4] = {};
    for (int k0 = 0; k0 < KP; k0 += 8) {
        STORE_A_PRE(pah, pal, arow, akp);
        STORE_B_SPLIT(pb0, pb1, kpB, ncol);
        __syncthreads();
        if (k0 + 8 < KP) {
#pragma unroll
            for (int i = 0; i < 2; i++) {
                pah[i] = *(const uint2*)(Ahp[i] + k0 + 8);
                pal[i] = *(const uint2*)(Alp[i] + k0 + 8);
            }
            pb0 = *(const float4*)(Bp0 + (size_t)(2 * (k0 + 8)) * D);
            pb1 = *(const float4*)(Bp1 + (size_t)(2 * (k0 + 8)) * D);
        }
        MMA_STEP16(mb, nb, lane, c);
        __syncthreads();
    }
#pragma unroll
    for (int mt = 0; mt < 4; mt++) {
        int rt = row0 + mb + mt * 16 + (lane >> 2);
#pragma unroll
        for (int half = 0; half < 2; half++) {
            int r = rt + half * 8;
            if (r >= cnt) continue;
            int tok = list[r];
            float gate = g_gfull[tok * NE + e];
#pragma unroll
            for (int nt = 0; nt < 4; nt++) {
                int cc = col0 + nb + nt * 8 + ((lane & 3) << 1);
                float* xp = g_x + (size_t)tok * D + cc;
                atomicAdd(xp + 0, gate * c[mt][nt][half * 2 + 0]);
                atomicAdd(xp + 1, gate * c[mt][nt][half * 2 + 1]);
            }
        }
    }
}

// ---------------- QKV weight pack (all layers, fp32) ----------------
__global__ void pack_qkv_kernel(const float* __restrict__ wq, const float* __restrict__ wk,
                                const float* __restrict__ wv) {
    int idx = blockIdx.x * blockDim.x + threadIdx.x;
    if (idx >= NLAYER * D * QKVW) return;
    int l = idx / (D * QKVW);
    int rest = idx - l * (D * QKVW);
    int d = rest / QKVW, c = rest % QKVW;
    float v;
    if (c < H * HD) v = wq[((size_t)l * D + d) * (H * HD) + c];
    else if (c < H * HD + KVH * HD) v = wk[((size_t)l * D + d) * (KVH * HD) + (c - H * HD)];
    else v = wv[((size_t)l * D + d) * (KVH * HD) + (c - H * HD - KVH * HD)];
    g_wqkv[idx] = v;
}

// ---------------- RoPE over packed qkv ----------------
__global__ void rope_kernel() {
    int idx = blockIdx.x * blockDim.x + threadIdx.x;
    const int total = NTOK * (H + KVH) * (HD / 2);
    if (idx >= total) return;
    int i = idx % (HD / 2);
    int rest = idx / (HD / 2);
    int hh = rest % (H + KVH);
    int n = rest / (H + KVH);
    int t = n % TT;
    int off = (hh < H) ? hh * HD : H * HD + (hh - H) * HD;
    float inv = exp2f(-((float)(2 * i) / (float)HD) * 19.9315685693241741f);
    float fr = (float)t * inv;
    float c, s;
    sincosf(fr, &s, &c);
    float* p = g_qkv + (size_t)n * QKVW + off + 2 * i;
    float x1 = p[0], x2 = p[1];
    p[0] = x1 * c - x2 * s;
    p[1] = x1 * s + x2 * c;
}

// ---------------- tiled causal attention (flash-style fp32, split output) --------
__global__ __launch_bounds__(256) void attn_kernel() {
    extern __shared__ float sm[];
    float* Qs = sm;
    float* Ks = sm + 64 * APAD;
    float* Vs = sm + 2 * 64 * APAD;
    int q0 = (gridDim.x - 1 - blockIdx.x) * QT;
    int h = blockIdx.y, b = blockIdx.z;
    int kvh = h / REP;
    int tid = threadIdx.x;
    int tx = tid & 15, ty = tid >> 4;
    const size_t qoff = (size_t)h * HD;
    const size_t koff = (size_t)(H * HD) + kvh * HD;
    const size_t voff = (size_t)(H * HD + KVH * HD) + kvh * HD;

    {
        int qi = tid & 63, c0 = (tid >> 6) * 16;
        const float* qp = g_qkv + (size_t)(b * TT + q0 + qi) * QKVW + qoff + c0;
#pragma unroll
        for (int t = 0; t < 4; t++) {
            float4 v = *(const float4*)(qp + 4 * t);
            Qs[(c0 + 4 * t + 0) * APAD + qi] = v.x;
            Qs[(c0 + 4 * t + 1) * APAD + qi] = v.y;
            Qs[(c0 + 4 * t + 2) * APAD + qi] = v.z;
            Qs[(c0 + 4 * t + 3) * APAD + qi] = v.w;
        }
    }

    float O[4][4] = {};
    float mrow[4], lrow[4];
#pragma unroll
    for (int i = 0; i < 4; i++) { mrow[i] = -1e30f; lrow[i] = 0.f; }

    int ntiles = q0 / QT + 1;
    for (int t0 = 0; t0 < ntiles; t0++) {
        int k0 = t0 * QT;
        __syncthreads();
        {
            int kj = tid & 63, c0 = (tid >> 6) * 16;
            const float* kpp = g_qkv + (size_t)(b * TT + k0 + kj) * QKVW + koff + c0;
            const float* vpp = g_qkv + (size_t)(b * TT + k0 + kj) * QKVW + voff + c0;
#pragma unroll
            for (int t = 0; t < 4; t++) {
                float4 v = *(const float4*)(kpp + 4 * t);
                Ks[(c0 + 4 * t + 0) * APAD + kj] = v.x;
                Ks[(c0 + 4 * t + 1) * APAD + kj] = v.y;
                Ks[(c0 + 4 * t + 2) * APAD + kj] = v.z;
                Ks[(c0 + 4 * t + 3) * APAD + kj] = v.w;
                *(float4*)&Vs[kj * APAD + c0 + 4 * t] = *(const float4*)(vpp + 4 * t);
            }
        }
        __syncthreads();
        float s[4][4] = {};
        for (int d = 0; d < HD; d++) {
            float4 a = *(const float4*)&Qs[d * APAD + ty * 4];
            float4 bq = *(const float4*)&Ks[d * APAD + tx * 4];
            const float av[4] = {a.x, a.y, a.z, a.w};
            const float bv[4] = {bq.x, bq.y, bq.z, bq.w};
#pragma unroll
            for (int i = 0; i < 4; i++)
#pragma unroll
                for (int j = 0; j < 4; j++) s[i][j] += av[i] * bv[j];
        }
#pragma unroll
        for (int i = 0; i < 4; i++)
#pragma unroll
            for (int j = 0; j < 4; j++) s[i][j] *= 0.125f;
        if (k0 == q0) {
#pragma unroll
            for (int i = 0; i < 4; i++)
#pragma unroll
                for (int j = 0; j < 4; j++)
                    if (k0 + tx * 4 + j > q0 + ty * 4 + i) s[i][j] = -1e30f;
        }
        __syncthreads();
#pragma unroll
        for (int i = 0; i < 4; i++) {
            float tm = fmaxf(fmaxf(s[i][0], s[i][1]), fmaxf(s[i][2], s[i][3]));
#pragma unroll
            for (int o = 8; o; o >>= 1) tm = fmaxf(tm, __shfl_xor_sync(0xffffffffu, tm, o));
            float mn = fmaxf(mrow[i], tm);
            float sc = expf(mrow[i] - mn);
            float p0 = expf(s[i][0] - mn), p1 = expf(s[i][1] - mn);
            float p2 = expf(s[i][2] - mn), p3 = expf(s[i][3] - mn);
            float rs = p0 + p1 + p2 + p3;
#pragma unroll
            for (int o = 8; o; o >>= 1) rs += __shfl_xor_sync(0xffffffffu, rs, o);
            lrow[i] = lrow[i] * sc + rs;
            mrow[i] = mn;
#pragma unroll
            for (int j = 0; j < 4; j++) O[i][j] *= sc;
            *(float4*)&Ks[(ty * 4 + i) * APAD + tx * 4] = make_float4(p0, p1, p2, p3);
        }
        __syncthreads();
        for (int kk = 0; kk < QT; kk++) {
            float4 vv = *(const float4*)&Vs[kk * APAD + tx * 4];
            const float vb[4] = {vv.x, vv.y, vv.z, vv.w};
            float a0 = Ks[(ty * 4 + 0) * APAD + kk];
            float a1 = Ks[(ty * 4 + 1) * APAD + kk];
            float a2 = Ks[(ty * 4 + 2) * APAD + kk];
            float a3 = Ks[(ty * 4 + 3) * APAD + kk];
#pragma unroll
            for (int j = 0; j < 4; j++) {
                O[0][j] += a0 * vb[j];
                O[1][j] += a1 * vb[j];
                O[2][j] += a2 * vb[j];
                O[3][j] += a3 * vb[j];
            }
        }
    }
    // write split output (consumed only by wo GEMM)
#pragma unroll
    for (int i = 0; i < 4; i++) {
        float inv = 1.f / lrow[i];
        float o0 = O[i][0] * inv, o1 = O[i][1] * inv;
        float o2 = O[i][2] * inv, o3 = O[i][3] * inv;
        uint32_t h0, l0, h1, l1;
        split2(o0, o1, h0, l0);
        split2(o2, o3, h1, l1);
        size_t n = (size_t)(b * TT + q0 + ty * 4 + i);
        size_t cp = n * (D / 2) + h * (HD / 2) + tx * 2;
        *(uint2*)&g_att_hi[cp] = make_uint2(h0, h1);
        *(uint2*)&g_att_lo[cp] = make_uint2(l0, l1);
    }
}

// ---------------- router: softmax + top-2 gates + expert list append ----------------
__global__ void router_kernel(const float* __restrict__ xn, const float* __restrict__ rw) {
    int n = blockIdx.x;
    int warp = threadIdx.x >> 5, lane = threadIdx.x & 31;
    __shared__ float sdot[NE];
    const float* xr = xn + (size_t)n * D;
    float acc = 0.f;
    for (int d = lane; d < D; d += 32) acc += xr[d] * rw[(size_t)d * NE + warp];
    for (int o = 16; o; o >>= 1) acc += __shfl_xor_sync(0xffffffffu, acc, o);
    if (lane == 0) sdot[warp] = acc;
    __syncthreads();
    if (threadIdx.x == 0) {
        float m = -1e30f;
        for (int e = 0; e < NE; e++) m = fmaxf(m, sdot[e]);
        float p[NE], s = 0.f;
        for (int e = 0; e < NE; e++) { p[e] = expf(sdot[e] - m); s += p[e]; }
        for (int e = 0; e < NE; e++) p[e] /= s;
        int i1 = 0;
        for (int e = 1; e < NE; e++) if (p[e] > p[i1]) i1 = e;
        int i2 = -1;
        for (int e = 0; e < NE; e++) {
            if (e == i1) continue;
            if (i2 < 0 || p[e] > p[i2]) i2 = e;
        }
        float gs = p[i1] + p[i2];
        for (int e = 0; e < NE; e++) {
            g_probs[n * NE + e] = p[e];
            g_gfull[n * NE + e] = (e == i1) ? p[i1] / gs : (e == i2 ? p[i2] / gs : 0.f);
        }
        int pos1 = atomicAdd(&g_cnt[i1], 1);
        g_list[i1 * NTOK + pos1] = n;
        int pos2 = atomicAdd(&g_cnt[i2], 1);
        g_list[i2 * NTOK + pos2] = n;
    }
}

// ---------------- expert count zero ----------------
__global__ void zero_cnt_kernel() {
    if (threadIdx.x < NE) g_cnt[threadIdx.x] = 0;
}

// ---------------- aux loss accumulate ----------------
__global__ void aux_kernel() {
    __shared__ float sme[NE], sce[NE];
    int tid = threadIdx.x;
    if (tid < NE) { sme[tid] = 0.f; sce[tid] = 0.f; }
    __syncthreads();
    float me[NE] = {}, ce[NE] = {};
    for (int n = tid; n < NTOK; n += blockDim.x)
        for (int e = 0; e < NE; e++) {
            me[e] += g_probs[n * NE + e];
            if (g_gfull[n * NE + e] > 0.f) ce[e] += 1.f;
        }
    for (int e = 0; e < NE; e++) { atomicAdd(&sme[e], me[e]); atomicAdd(&sce[e], ce[e]); }
    __syncthreads();
    if (tid == 0) {
        float a = 0.f;
        for (int e = 0; e < NE; e++)
            a += (sme[e] / NTOK) * (sce[e] / (float)(NTOK * KTOP));
        g_aux[0] += NE * a;
    }
}

__global__ void zero_aux_kernel() { g_aux[0] = 0.f; }

// ---------------- final heads ----------------
__global__ void mean_kernel() {
    int idx = blockIdx.x * blockDim.x + threadIdx.x;
    if (idx >= BB * D) return;
    int b = idx / D, d = idx % D;
    float s = 0.f;
    for (int t = 0; t < TT; t++) s += g_norm[(size_t)(b * TT + t) * D + d];
    g_xmean[idx] = s / TT;
}

__global__ void task_head_kernel(const float* __restrict__ tw, const float* __restrict__ tb,
                                 float* __restrict__ out) {
    int b = blockIdx.x;
    int j = threadIdx.x >> 5, lane = threadIdx.x & 31;
    if (j >= NTASK) return;
    const float* xr = g_norm + (size_t)(b * TT) * D;
    float a = 0.f;
    for (int d = lane; d < D; d += 32) a += xr[d] * tw[(size_t)d * NTASK + j];
    for (int o = 16; o; o >>= 1) a += __shfl_xor_sync(0xffffffffu, a, o);
    if (lane == 0) out[b * NTASK + j] = a + tb[j];
}

__global__ void eval_head_kernel(const float* __restrict__ ew, const float* __restrict__ eb,
                                 float* __restrict__ out) {
    int b = blockIdx.x;
    int j = threadIdx.x >> 5, lane = threadIdx.x & 31;
    if (j >= NEVAL) return;
    const float* xr = g_xmean + (size_t)b * D;
    float a = 0.f;
    for (int d = lane; d < D; d += 32) a += xr[d] * ew[(size_t)d * NEVAL + j];
    for (int o = 16; o; o >>= 1) a += __shfl_xor_sync(0xffffffffu, a, o);
    if (lane == 0) out[b * NEVAL + j] = a + eb[j];
}

__global__ void write_aux_kernel(float* __restrict__ out) { out[0] = g_aux[0]; }

// ---------------- host orchestration ----------------
extern "C" void kernel_launch(void* const* d_in, const int* in_sizes, int n_in,
                              void* d_out, int out_size) {
    const int*   ids     = (const int*)d_in[0];
    const float* embed_w = (const float*)d_in[1];
    const float* wq      = (const float*)d_in[2];
    const float* wk      = (const float*)d_in[3];
    const float* wv      = (const float*)d_in[4];
    const float* wo      = (const float*)d_in[5];
    const float* n1w     = (const float*)d_in[6];
    const float* n2w     = (const float*)d_in[7];
    const float* rw      = (const float*)d_in[8];
    const float* wg      = (const float*)d_in[9];
    const float* wu      = (const float*)d_in[10];
    const float* wd      = (const float*)d_in[11];
    const float* nfw     = (const float*)d_in[12];
    const float* lmw     = (const float*)d_in[13];
    const float* tw      = (const float*)d_in[14];
    const float* tb      = (const float*)d_in[15];
    const float* evw     = (const float*)d_in[16];
    const float* evb     = (const float*)d_in[17];
    float* out = (float*)d_out;

    float *p_x, *p_norm, *p_wqkv, *p_qkv;
    uint32_t *p_nh, *p_nl, *p_ath, *p_atl;
    cudaGetSymbolAddress((void**)&p_x, g_x);
    cudaGetSymbolAddress((void**)&p_norm, g_norm);
    cudaGetSymbolAddress((void**)&p_wqkv, g_wqkv);
    cudaGetSymbolAddress((void**)&p_qkv, g_qkv);
    cudaGetSymbolAddress((void**)&p_nh, g_norm_hi);
    cudaGetSymbolAddress((void**)&p_nl, g_norm_lo);
    cudaGetSymbolAddress((void**)&p_ath, g_att_hi);
    cudaGetSymbolAddress((void**)&p_atl, g_att_lo);

    cudaFuncSetAttribute(attn_kernel, cudaFuncAttributeMaxDynamicSharedMemorySize, ATTN_SMEM);

    embed_kernel<<<NTOK, 256>>>(ids, embed_w);
    zero_aux_kernel<<<1, 1>>>();
    {
        int tot = NLAYER * D * QKVW;
        pack_qkv_kernel<<<(tot + 255) / 256, 256>>>(wq, wk, wv);
    }

    for (int l = 0; l < NLAYER; l++) {
        // ---- attention block ----
        rmsnorm_kernel<<<NTOK, 256>>>(p_x, n1w + (size_t)l * D, p_norm);
        gemm(p_nh, p_nl, p_wqkv + (size_t)l * D * QKVW, p_qkv, NTOK, QKVW, D);
        {
            int tot = NTOK * (H + KVH) * (HD / 2);
            rope_kernel<<<(tot + 255) / 256, 256>>>();
        }
        {
            dim3 ag(TT / QT, H, BB);
            attn_kernel<<<ag, 256, ATTN_SMEM>>>();
        }
        gemm(p_ath, p_atl, wo + (size_t)l * (H * HD) * D, p_x, NTOK, D, H * HD, /*accum=*/1);

        // ---- MoE block (sparse top-2) ----
        rmsnorm_kernel<<<NTOK, 256>>>(p_x, n2w + (size_t)l * D, p_norm);
        zero_cnt_kernel<<<1, 32>>>();
        router_kernel<<<NTOK, 256>>>(p_norm, rw + (size_t)l * D * NE);
        aux_kernel<<<1, 256>>>();
        {
            dim3 gu(NTOK / TM, FF / TN, NE * 2);
            moe_up_gemm<<<gu, 256>>>(wg + (size_t)l * NE * D * FF,
                                     wu + (size_t)l * NE * D * FF);
            dim3 gs(NTOK, NE);
            silu_split_kernel<<<gs, 256>>>();
            dim3 gdn(NTOK / TM, D / TN, NE);
            moe_down_gemm<<<gdn, 256>>>(wd + (size_t)l * NE * FF * D);
        }
    }

    // ---- final norm + heads ----
    rmsnorm_kernel<<<NTOK, 256>>>(p_x, nfw, p_norm);
    gemm(p_nh, p_nl, lmw, out, NTOK, VOCAB, D);

    const size_t LOGITS = (size_t)NTOK * VOCAB;
    task_head_kernel<<<BB, 32 * NTASK>>>(tw, tb, out + LOGITS);
    mean_kernel<<<(BB * D + 255) / 256, 256>>>();
    eval_head_kernel<<<BB, 32 * NEVAL>>>(evw, evb, out + LOGITS + BB * NTASK);
    write_aux_kernel<<<1, 1>>>(out + LOGITS + BB * NTASK + BB * NEVAL);
}

// round 15
// speedup vs baseline: 1.0587x; 1.0587x over previous
#include <cuda_runtime.h>
#include <cuda_bf16.h>
#include <math.h>
#include <stdint.h>

#define NLAYER 4
#define D 1024
#define H 16
#define KVH 4
#define HD 64
#define NE 8
#define KTOP 2
#define FF 512
#define VOCAB 32000
#define BB 2
#define TT 1024
#define NTASK 10
#define NEVAL 5
#define NTOK (BB*TT)
#define EPSV 1e-6f
#define REP (H/KVH)
#define QKVW (H*HD + 2*KVH*HD)   // 1536

#define TM 128
#define TN 128
#define TK 16

#define QT 64
#define APAD 68
#define ATTN_SMEM (3*64*APAD*4)

// ---------------- scratch (device globals; no allocations) ----------------
__device__ float g_x[NTOK*D];
__device__ float g_norm[NTOK*D];
__device__ float g_qkv[NTOK*QKVW];
__device__ float g_wqkv[NLAYER*D*QKVW];
__device__ float g_att[NTOK*D];
__device__ float g_hg[NE*NTOK*FF];
__device__ float g_hu[NE*NTOK*FF];
__device__ float g_probs[NTOK*NE];
__device__ float g_gfull[NTOK*NE];
__device__ int   g_cnt[NE];
__device__ int   g_list[NE*NTOK];
__device__ float g_aux[1];
__device__ float g_xmean[BB*D];

// ---------------- helpers ----------------
// pack two floats to bf16x2: low half = first arg
__device__ __forceinline__ uint32_t packbf(float lo_v, float hi_v) {
    uint32_t r;
    asm("cvt.rn.bf16x2.f32 %0, %1, %2;" : "=r"(r) : "f"(hi_v), "f"(lo_v));
    return r;
}

// split consecutive-k pair (x,y) into hi/lo bf16x2 words
__device__ __forceinline__ void split2(float x, float y, uint32_t& hi, uint32_t& lo) {
    hi = packbf(x, y);
    __nv_bfloat162 h2 = *reinterpret_cast<__nv_bfloat162*>(&hi);
    float rx = x - __bfloat162float(h2.x);
    float ry = y - __bfloat162float(h2.y);
    lo = packbf(rx, ry);
}

__device__ __forceinline__ void mma_bf16(float (&c)[4], uint32_t a0, uint32_t a1,
                                         uint32_t a2, uint32_t a3, uint32_t b0, uint32_t b1) {
    asm volatile(
        "mma.sync.aligned.m16n8k16.row.col.f32.bf16.bf16.f32 "
        "{%0,%1,%2,%3}, {%4,%5,%6,%7}, {%8,%9}, {%0,%1,%2,%3};"
        : "+f"(c[0]), "+f"(c[1]), "+f"(c[2]), "+f"(c[3])
        : "r"(a0), "r"(a1), "r"(a2), "r"(a3), "r"(b0), "r"(b1));
}

__device__ __forceinline__ float siluf(float g) { return g / (1.f + expf(-g)); }

__device__ __forceinline__ float4 silu_mul4(float4 g, float4 u) {
    float4 r;
    r.x = siluf(g.x) * u.x;
    r.y = siluf(g.y) * u.y;
    r.z = siluf(g.z) * u.z;
    r.w = siluf(g.w) * u.w;
    return r;
}

#define GEMM_SMEM_DECL                                \
    __shared__ uint32_t Ahi[8][TM + 8];               \
    __shared__ uint32_t Alo[8][TM + 8];               \
    __shared__ uint32_t Bhi[8][TN + 8];               \
    __shared__ uint32_t Blo[8][TN + 8];

// store A float4 (4 consecutive k) as two hi/lo bf16x2 pairs, transposed
#define STORE_A(pa, acol, r)                                                  \
    do {                                                                       \
        split2(pa.x, pa.y, Ahi[(acol) >> 1][r], Alo[(acol) >> 1][r]);          \
        split2(pa.z, pa.w, Ahi[((acol) >> 1) + 1][r], Alo[((acol) >> 1) + 1][r]);\
    } while (0)

// store B k-pair rows (pb0 = row 2kp, pb1 = row 2kp+1) packed by k
#define STORE_B(pb0, pb1, kp, ncol)                                           \
    do {                                                                       \
        split2(pb0.x, pb1.x, Bhi[kp][(ncol) + 0], Blo[kp][(ncol) + 0]);        \
        split2(pb0.y, pb1.y, Bhi[kp][(ncol) + 1], Blo[kp][(ncol) + 1]);        \
        split2(pb0.z, pb1.z, Bhi[kp][(ncol) + 2], Blo[kp][(ncol) + 2]);        \
        split2(pb0.w, pb1.w, Bhi[kp][(ncol) + 3], Blo[kp][(ncol) + 3]);        \
    } while (0)

// one 16-k step of 3-product bf16 emulated-fp32 mma
#define MMA_STEP16(mb, nb, lane, c)                                           \
    do {                                                                       \
        int kq = (lane) & 3;                                                   \
        int mrw = (lane) >> 2;                                                 \
        uint32_t ah[4][4], al[4][4], bh[4][2], bl[4][2];                       \
        _Pragma("unroll") for (int mt = 0; mt < 4; mt++) {                     \
            int m = (mb) + mt * 16 + mrw;                                      \
            ah[mt][0] = Ahi[kq][m];     ah[mt][1] = Ahi[kq][m + 8];            \
            ah[mt][2] = Ahi[kq + 4][m]; ah[mt][3] = Ahi[kq + 4][m + 8];        \
            al[mt][0] = Alo[kq][m];     al[mt][1] = Alo[kq][m + 8];            \
            al[mt][2] = Alo[kq + 4][m]; al[mt][3] = Alo[kq + 4][m + 8];        \
        }                                                                      \
        _Pragma("unroll") for (int nt = 0; nt < 4; nt++) {                     \
            int n = (nb) + nt * 8 + mrw;                                       \
            bh[nt][0] = Bhi[kq][n]; bh[nt][1] = Bhi[kq + 4][n];                \
            bl[nt][0] = Blo[kq][n]; bl[nt][1] = Blo[kq + 4][n];                \
        }                                                                      \
        _Pragma("unroll") for (int mt = 0; mt < 4; mt++)                       \
            _Pragma("unroll") for (int nt = 0; nt < 4; nt++) {                 \
                mma_bf16(c[mt][nt], ah[mt][0], ah[mt][1], ah[mt][2],           \
                         ah[mt][3], bl[nt][0], bl[nt][1]);                     \
                mma_bf16(c[mt][nt], al[mt][0], al[mt][1], al[mt][2],           \
                         al[mt][3], bh[nt][0], bh[nt][1]);                     \
                mma_bf16(c[mt][nt], ah[mt][0], ah[mt][1], ah[mt][2],           \
                         ah[mt][3], bh[nt][0], bh[nt][1]);                     \
            }                                                                  \
    } while (0)

// ---------------- embedding gather ----------------
__global__ void embed_kernel(const int* __restrict__ ids, const float* __restrict__ ew) {
    int n = blockIdx.x;
    int id = ids[n];
    const float* src = ew + (size_t)id * D;
    float* dst = g_x + (size_t)n * D;
    for (int d = threadIdx.x; d < D; d += blockDim.x) dst[d] = src[d];
}

// ---------------- rmsnorm ----------------
__global__ void rmsnorm_kernel(const float* __restrict__ x, const float* __restrict__ w,
                               float* __restrict__ out) {
    int n = blockIdx.x;
    const float* xr = x + (size_t)n * D;
    float s = 0.f;
    for (int d = threadIdx.x; d < D; d += blockDim.x) { float v = xr[d]; s += v * v; }
    for (int o = 16; o; o >>= 1) s += __shfl_xor_sync(0xffffffffu, s, o);
    __shared__ float rb[8];
    if ((threadIdx.x & 31) == 0) rb[threadIdx.x >> 5] = s;
    __syncthreads();
    __shared__ float srms;
    if (threadIdx.x == 0) {
        float t = 0.f;
        for (int i = 0; i < 8; i++) t += rb[i];
        srms = rsqrtf(t / D + EPSV);
    }
    __syncthreads();
    float rms = srms;
    float* o2 = out + (size_t)n * D;
    for (int d = threadIdx.x; d < D; d += blockDim.x) o2[d] = w[d] * xr[d] * rms;
}

// ================= bf16x3 tensor-core GEMM (dense, single buffer — R6) =============
// C[M,N] (+)= A[M,K] @ B[K,N].  N%128==0, K%16==0.
__global__ __launch_bounds__(256) void gemm_bf16(
    const float* __restrict__ A, const float* __restrict__ B, float* __restrict__ C,
    int M, int N, int K, int accum) {
    GEMM_SMEM_DECL
    int tid = threadIdx.x;
    int row0 = blockIdx.y * TM;
    int col0 = blockIdx.x * TN;
    if (row0 >= M) return;
    int lane = tid & 31, w = tid >> 5;
    int mb = (w & 1) * 64, nb = (w >> 1) * 32;
    int arow = tid >> 2, acol = (tid & 3) << 2;
    int kp = tid >> 5, ncol = (tid & 31) << 2;

    const float* Aptr[2]; bool av[2];
#pragma unroll
    for (int i = 0; i < 2; i++) {
        int r = row0 + arow + i * 64;
        av[i] = (r < M);
        Aptr[i] = A + (size_t)(av[i] ? r : (M - 1)) * K + acol;
    }
    const float* Bp0 = B + (size_t)(2 * kp) * N + col0 + ncol;
    const float* Bp1 = Bp0 + N;

    float4 pa[2], pb0, pb1;
#pragma unroll
    for (int i = 0; i < 2; i++)
        pa[i] = av[i] ? *(const float4*)(Aptr[i]) : make_float4(0.f, 0.f, 0.f, 0.f);
    pb0 = *(const float4*)(Bp0);
    pb1 = *(const float4*)(Bp1);

    float c[4][4][4] = {};
    for (int k0 = 0; k0 < K; k0 += TK) {
#pragma unroll
        for (int i = 0; i < 2; i++) STORE_A(pa[i], acol, arow + i * 64);
        STORE_B(pb0, pb1, kp, ncol);
        __syncthreads();
        if (k0 + TK < K) {
#pragma unroll
            for (int i = 0; i < 2; i++)
                pa[i] = av[i] ? *(const float4*)(Aptr[i] + k0 + TK) : make_float4(0.f, 0.f, 0.f, 0.f);
            pb0 = *(const float4*)(Bp0 + (size_t)(k0 + TK) * N);
            pb1 = *(const float4*)(Bp1 + (size_t)(k0 + TK) * N);
        }
        MMA_STEP16(mb, nb, lane, c);
        __syncthreads();
    }
#pragma unroll
    for (int mt = 0; mt < 4; mt++) {
        int rt = row0 + mb + mt * 16 + (lane >> 2);
#pragma unroll
        for (int nt = 0; nt < 4; nt++) {
            int cc = col0 + nb + nt * 8 + ((lane & 3) << 1);
            if (rt < M) {
                float2* p = (float2*)&C[(size_t)rt * N + cc];
                float2 v = make_float2(c[mt][nt][0], c[mt][nt][1]);
                if (accum) { float2 o = *p; v.x += o.x; v.y += o.y; }
                *p = v;
            }
            if (rt + 8 < M) {
                float2* p = (float2*)&C[(size_t)(rt + 8) * N + cc];
                float2 v = make_float2(c[mt][nt][2], c[mt][nt][3]);
                if (accum) { float2 o = *p; v.x += o.x; v.y += o.y; }
                *p = v;
            }
        }
    }
}

static inline void gemm(const float* A, const float* B, float* C, int M, int N, int K,
                        int accum = 0) {
    dim3 grid(N / TN, (M + TM - 1) / TM);
    gemm_bf16<<<grid, 256>>>(A, B, C, M, N, K, accum);
}

// ================= MoE up/gate GEMM (gathered A, bf16x3 — R6) =================
__global__ __launch_bounds__(256) void moe_up_gemm(
    const float* __restrict__ Xn, const float* __restrict__ Wg, const float* __restrict__ Wu) {
    int z = blockIdx.z;
    int e = z >> 1, u = z & 1;
    int cnt = g_cnt[e];
    int row0 = blockIdx.y * TM;
    if (row0 >= cnt) return;
    GEMM_SMEM_DECL
    int tid = threadIdx.x;
    int col0 = blockIdx.x * TN;
    int lane = tid & 31, w = tid >> 5;
    int mb = (w & 1) * 64, nb = (w >> 1) * 32;
    int arow = tid >> 2, acol = (tid & 3) << 2;
    int kp = tid >> 5, ncol = (tid & 31) << 2;
    const int* list = g_list + e * NTOK;
    const float* B = (u ? Wu : Wg) + (size_t)e * D * FF;
    float* C = (u ? g_hu : g_hg) + (size_t)e * NTOK * FF;

    const float* Aptr[2]; bool av[2];
#pragma unroll
    for (int i = 0; i < 2; i++) {
        int r = row0 + arow + i * 64;
        av[i] = (r < cnt);
        Aptr[i] = Xn + (size_t)list[av[i] ? r : (cnt - 1)] * D + acol;
    }
    const float* Bp0 = B + (size_t)(2 * kp) * FF + col0 + ncol;
    const float* Bp1 = Bp0 + FF;

    float4 pa[2], pb0, pb1;
#pragma unroll
    for (int i = 0; i < 2; i++)
        pa[i] = av[i] ? *(const float4*)(Aptr[i]) : make_float4(0.f, 0.f, 0.f, 0.f);
    pb0 = *(const float4*)(Bp0);
    pb1 = *(const float4*)(Bp1);

    float c[4][4][4] = {};
    for (int k0 = 0; k0 < D; k0 += TK) {
#pragma unroll
        for (int i = 0; i < 2; i++) STORE_A(pa[i], acol, arow + i * 64);
        STORE_B(pb0, pb1, kp, ncol);
        __syncthreads();
        if (k0 + TK < D) {
#pragma unroll
            for (int i = 0; i < 2; i++)
                pa[i] = av[i] ? *(const float4*)(Aptr[i] + k0 + TK) : make_float4(0.f, 0.f, 0.f, 0.f);
            pb0 = *(const float4*)(Bp0 + (size_t)(k0 + TK) * FF);
            pb1 = *(const float4*)(Bp1 + (size_t)(k0 + TK) * FF);
        }
        MMA_STEP16(mb, nb, lane, c);
        __syncthreads();
    }
#pragma unroll
    for (int mt = 0; mt < 4; mt++) {
        int rt = row0 + mb + mt * 16 + (lane >> 2);
#pragma unroll
        for (int nt = 0; nt < 4; nt++) {
            int cc = col0 + nb + nt * 8 + ((lane & 3) << 1);
            if (rt < cnt)
                *(float2*)&C[(size_t)rt * FF + cc] = make_float2(c[mt][nt][0], c[mt][nt][1]);
            if (rt + 8 < cnt)
                *(float2*)&C[(size_t)(rt + 8) * FF + cc] = make_float2(c[mt][nt][2], c[mt][nt][3]);
        }
    }
}

// ========== MoE down GEMM (silu-fused A, gated scatter-add, bf16x3 — R6) ==========
__global__ __launch_bounds__(256) void moe_down_gemm(const float* __restrict__ Wd) {
    int e = blockIdx.z;
    int cnt = g_cnt[e];
    int row0 = blockIdx.y * TM;
    if (row0 >= cnt) return;
    GEMM_SMEM_DECL
    int tid = threadIdx.x;
    int col0 = blockIdx.x * TN;
    int lane = tid & 31, w = tid >> 5;
    int mb = (w & 1) * 64, nb = (w >> 1) * 32;
    int arow = tid >> 2, acol = (tid & 3) << 2;
    int kp = tid >> 5, ncol = (tid & 31) << 2;
    const int* list = g_list + e * NTOK;
    const float* hgB = g_hg + (size_t)e * NTOK * FF;
    const float* huB = g_hu + (size_t)e * NTOK * FF;
    const float* B = Wd + (size_t)e * FF * D;

    const float* gp[2]; const float* up[2]; bool av[2];
#pragma unroll
    for (int i = 0; i < 2; i++) {
        int r = row0 + arow + i * 64;
        av[i] = (r < cnt);
        int rc = av[i] ? r : (cnt - 1);
        gp[i] = hgB + (size_t)rc * FF + acol;
        up[i] = huB + (size_t)rc * FF + acol;
    }
    const float* Bp0 = B + (size_t)(2 * kp) * D + col0 + ncol;
    const float* Bp1 = Bp0 + D;

    float4 pa[2], pb0, pb1;
#pragma unroll
    for (int i = 0; i < 2; i++)
        pa[i] = av[i] ? silu_mul4(*(const float4*)gp[i], *(const float4*)up[i])
                      : make_float4(0.f, 0.f, 0.f, 0.f);
    pb0 = *(const float4*)(Bp0);
    pb1 = *(const float4*)(Bp1);

    float c[4][4][4] = {};
    for (int k0 = 0; k0 < FF; k0 += TK) {
#pragma unroll
        for (int i = 0; i < 2; i++) STORE_A(pa[i], acol, arow + i * 64);
        STORE_B(pb0, pb1, kp, ncol);
        __syncthreads();
        if (k0 + TK < FF) {
#pragma unroll
            for (int i = 0; i < 2; i++)
                pa[i] = av[i] ? silu_mul4(*(const float4*)(gp[i] + k0 + TK),
                                          *(const float4*)(up[i] + k0 + TK))
                              : make_float4(0.f, 0.f, 0.f, 0.f);
            pb0 = *(const float4*)(Bp0 + (size_t)(k0 + TK) * D);
            pb1 = *(const float4*)(Bp1 + (size_t)(k0 + TK) * D);
        }
        MMA_STEP16(mb, nb, lane, c);
        __syncthreads();
    }
#pragma unroll
    for (int mt = 0; mt < 4; mt++) {
        int rt = row0 + mb + mt * 16 + (lane >> 2);
#pragma unroll
        for (int half = 0; half < 2; half++) {
            int r = rt + half * 8;
            if (r >= cnt) continue;
            int tok = list[r];
            float gate = g_gfull[tok * NE + e];
#pragma unroll
            for (int nt = 0; nt < 4; nt++) {
                int cc = col0 + nb + nt * 8 + ((lane & 3) << 1);
                float* xp = g_x + (size_t)tok * D + cc;
                atomicAdd(xp + 0, gate * c[mt][nt][half * 2 + 0]);
                atomicAdd(xp + 1, gate * c[mt][nt][half * 2 + 1]);
            }
        }
    }
}

// ---------------- QKV weight pack (all layers at once) ----------------
__global__ void pack_qkv_kernel(const float* __restrict__ wq, const float* __restrict__ wk,
                                const float* __restrict__ wv) {
    int idx = blockIdx.x * blockDim.x + threadIdx.x;
    if (idx >= NLAYER * D * QKVW) return;
    int l = idx / (D * QKVW);
    int rest = idx - l * (D * QKVW);
    int d = rest / QKVW, c = rest % QKVW;
    float v;
    if (c < H * HD) v = wq[((size_t)l * D + d) * (H * HD) + c];
    else if (c < H * HD + KVH * HD) v = wk[((size_t)l * D + d) * (KVH * HD) + (c - H * HD)];
    else v = wv[((size_t)l * D + d) * (KVH * HD) + (c - H * HD - KVH * HD)];
    g_wqkv[idx] = v;
}

// ---------------- RoPE over packed qkv (q and k heads in one launch) ----------------
__global__ void rope_kernel() {
    int idx = blockIdx.x * blockDim.x + threadIdx.x;
    const int total = NTOK * (H + KVH) * (HD / 2);
    if (idx >= total) return;
    int i = idx % (HD / 2);
    int rest = idx / (HD / 2);
    int hh = rest % (H + KVH);
    int n = rest / (H + KVH);
    int t = n % TT;
    int off = (hh < H) ? hh * HD : H * HD + (hh - H) * HD;
    float inv = exp2f(-((float)(2 * i) / (float)HD) * 19.9315685693241741f);
    float fr = (float)t * inv;
    float c, s;
    sincosf(fr, &s, &c);
    float* p = g_qkv + (size_t)n * QKVW + off + 2 * i;
    float x1 = p[0], x2 = p[1];
    p[0] = x1 * c - x2 * s;
    p[1] = x1 * s + x2 * c;
}

// ---------------- tiled causal attention (flash-style, fp32 — R6) ----------------
__global__ __launch_bounds__(256) void attn_kernel() {
    extern __shared__ float sm[];
    float* Qs = sm;
    float* Ks = sm + 64 * APAD;
    float* Vs = sm + 2 * 64 * APAD;
    int q0 = (gridDim.x - 1 - blockIdx.x) * QT;
    int h = blockIdx.y, b = blockIdx.z;
    int kvh = h / REP;
    int tid = threadIdx.x;
    int tx = tid & 15, ty = tid >> 4;
    const size_t qoff = (size_t)h * HD;
    const size_t koff = (size_t)(H * HD) + kvh * HD;
    const size_t voff = (size_t)(H * HD + KVH * HD) + kvh * HD;

    {
        int qi = tid & 63, c0 = (tid >> 6) * 16;
        const float* qp = g_qkv + (size_t)(b * TT + q0 + qi) * QKVW + qoff + c0;
#pragma unroll
        for (int t = 0; t < 4; t++) {
            float4 v = *(const float4*)(qp + 4 * t);
            Qs[(c0 + 4 * t + 0) * APAD + qi] = v.x;
            Qs[(c0 + 4 * t + 1) * APAD + qi] = v.y;
            Qs[(c0 + 4 * t + 2) * APAD + qi] = v.z;
            Qs[(c0 + 4 * t + 3) * APAD + qi] = v.w;
        }
    }

    float O[4][4] = {};
    float mrow[4], lrow[4];
#pragma unroll
    for (int i = 0; i < 4; i++) { mrow[i] = -1e30f; lrow[i] = 0.f; }

    int ntiles = q0 / QT + 1;
    for (int t0 = 0; t0 < ntiles; t0++) {
        int k0 = t0 * QT;
        __syncthreads();
        {
            int kj = tid & 63, c0 = (tid >> 6) * 16;
            const float* kpp = g_qkv + (size_t)(b * TT + k0 + kj) * QKVW + koff + c0;
            const float* vpp = g_qkv + (size_t)(b * TT + k0 + kj) * QKVW + voff + c0;
#pragma unroll
            for (int t = 0; t < 4; t++) {
                float4 v = *(const float4*)(kpp + 4 * t);
                Ks[(c0 + 4 * t + 0) * APAD + kj] = v.x;
                Ks[(c0 + 4 * t + 1) * APAD + kj] = v.y;
                Ks[(c0 + 4 * t + 2) * APAD + kj] = v.z;
                Ks[(c0 + 4 * t + 3) * APAD + kj] = v.w;
                *(float4*)&Vs[kj * APAD + c0 + 4 * t] = *(const float4*)(vpp + 4 * t);
            }
        }
        __syncthreads();
        float s[4][4] = {};
        for (int d = 0; d < HD; d++) {
            float4 a = *(const float4*)&Qs[d * APAD + ty * 4];
            float4 bq = *(const float4*)&Ks[d * APAD + tx * 4];
            const float av[4] = {a.x, a.y, a.z, a.w};
            const float bv[4] = {bq.x, bq.y, bq.z, bq.w};
#pragma unroll
            for (int i = 0; i < 4; i++)
#pragma unroll
                for (int j = 0; j < 4; j++) s[i][j] += av[i] * bv[j];
        }
#pragma unroll
        for (int i = 0; i < 4; i++)
#pragma unroll
            for (int j = 0; j < 4; j++) s[i][j] *= 0.125f;
        if (k0 == q0) {
#pragma unroll
            for (int i = 0; i < 4; i++)
#pragma unroll
                for (int j = 0; j < 4; j++)
                    if (k0 + tx * 4 + j > q0 + ty * 4 + i) s[i][j] = -1e30f;
        }
        __syncthreads();
#pragma unroll
        for (int i = 0; i < 4; i++) {
            float tm = fmaxf(fmaxf(s[i][0], s[i][1]), fmaxf(s[i][2], s[i][3]));
#pragma unroll
            for (int o = 8; o; o >>= 1) tm = fmaxf(tm, __shfl_xor_sync(0xffffffffu, tm, o));
            float mn = fmaxf(mrow[i], tm);
            float sc = expf(mrow[i] - mn);
            float p0 = expf(s[i][0] - mn), p1 = expf(s[i][1] - mn);
            float p2 = expf(s[i][2] - mn), p3 = expf(s[i][3] - mn);
            float rs = p0 + p1 + p2 + p3;
#pragma unroll
            for (int o = 8; o; o >>= 1) rs += __shfl_xor_sync(0xffffffffu, rs, o);
            lrow[i] = lrow[i] * sc + rs;
            mrow[i] = mn;
#pragma unroll
            for (int j = 0; j < 4; j++) O[i][j] *= sc;
            *(float4*)&Ks[(ty * 4 + i) * APAD + tx * 4] = make_float4(p0, p1, p2, p3);
        }
        __syncthreads();
        for (int kk = 0; kk < QT; kk++) {
            float4 vv = *(const float4*)&Vs[kk * APAD + tx * 4];
            const float vb[4] = {vv.x, vv.y, vv.z, vv.w};
            float a0 = Ks[(ty * 4 + 0) * APAD + kk];
            float a1 = Ks[(ty * 4 + 1) * APAD + kk];
            float a2 = Ks[(ty * 4 + 2) * APAD + kk];
            float a3 = Ks[(ty * 4 + 3) * APAD + kk];
#pragma unroll
            for (int j = 0; j < 4; j++) {
                O[0][j] += a0 * vb[j];
                O[1][j] += a1 * vb[j];
                O[2][j] += a2 * vb[j];
                O[3][j] += a3 * vb[j];
            }
        }
    }
#pragma unroll
    for (int i = 0; i < 4; i++) {
        float inv = 1.f / lrow[i];
        float4 o = make_float4(O[i][0] * inv, O[i][1] * inv, O[i][2] * inv, O[i][3] * inv);
        *(float4*)&g_att[(size_t)(b * TT + q0 + ty * 4 + i) * D + h * HD + tx * 4] = o;
    }
}

// ------- router: softmax + top-2 gates + expert list append (R13-validated) -------
__global__ void router_kernel(const float* __restrict__ xn, const float* __restrict__ rw) {
    int n = blockIdx.x;
    int warp = threadIdx.x >> 5, lane = threadIdx.x & 31;
    __shared__ float sdot[NE];
    const float* xr = xn + (size_t)n * D;
    float acc = 0.f;
    for (int d = lane; d < D; d += 32) acc += xr[d] * rw[(size_t)d * NE + warp];
    for (int o = 16; o; o >>= 1) acc += __shfl_xor_sync(0xffffffffu, acc, o);
    if (lane == 0) sdot[warp] = acc;
    __syncthreads();
    if (threadIdx.x == 0) {
        float m = -1e30f;
        for (int e = 0; e < NE; e++) m = fmaxf(m, sdot[e]);
        float p[NE], s = 0.f;
        for (int e = 0; e < NE; e++) { p[e] = expf(sdot[e] - m); s += p[e]; }
        for (int e = 0; e < NE; e++) p[e] /= s;
        int i1 = 0;
        for (int e = 1; e < NE; e++) if (p[e] > p[i1]) i1 = e;
        int i2 = -1;
        for (int e = 0; e < NE; e++) {
            if (e == i1) continue;
            if (i2 < 0 || p[e] > p[i2]) i2 = e;
        }
        float gs = p[i1] + p[i2];
        for (int e = 0; e < NE; e++) {
            g_probs[n * NE + e] = p[e];
            g_gfull[n * NE + e] = (e == i1) ? p[i1] / gs : (e == i2 ? p[i2] / gs : 0.f);
        }
        int pos1 = atomicAdd(&g_cnt[i1], 1);
        g_list[i1 * NTOK + pos1] = n;
        int pos2 = atomicAdd(&g_cnt[i2], 1);
        g_list[i2 * NTOK + pos2] = n;
    }
}

// ---------------- expert count zero ----------------
__global__ void zero_cnt_kernel() {
    if (threadIdx.x < NE) g_cnt[threadIdx.x] = 0;
}

// ---------------- aux loss accumulate ----------------
__global__ void aux_kernel() {
    __shared__ float sme[NE], sce[NE];
    int tid = threadIdx.x;
    if (tid < NE) { sme[tid] = 0.f; sce[tid] = 0.f; }
    __syncthreads();
    float me[NE] = {}, ce[NE] = {};
    for (int n = tid; n < NTOK; n += blockDim.x)
        for (int e = 0; e < NE; e++) {
            me[e] += g_probs[n * NE + e];
            if (g_gfull[n * NE + e] > 0.f) ce[e] += 1.f;
        }
    for (int e = 0; e < NE; e++) { atomicAdd(&sme[e], me[e]); atomicAdd(&sce[e], ce[e]); }
    __syncthreads();
    if (tid == 0) {
        float a = 0.f;
        for (int e = 0; e < NE; e++)
            a += (sme[e] / NTOK) * (sce[e] / (float)(NTOK * KTOP));
        g_aux[0] += NE * a;
    }
}

__global__ void zero_aux_kernel() { g_aux[0] = 0.f; }

// ---------------- silu-mul (kept fused in down GEMM; no standalone pass) ----------

// ---------------- final heads ----------------
__global__ void mean_kernel() {
    int idx = blockIdx.x * blockDim.x + threadIdx.x;
    if (idx >= BB * D) return;
    int b = idx / D, d = idx % D;
    float s = 0.f;
    for (int t = 0; t < TT; t++) s += g_norm[(size_t)(b * TT + t) * D + d];
    g_xmean[idx] = s / TT;
}

__global__ void task_head_kernel(const float* __restrict__ tw, const float* __restrict__ tb,
                                 float* __restrict__ out) {
    int b = blockIdx.x;
    int j = threadIdx.x >> 5, lane = threadIdx.x & 31;
    if (j >= NTASK) return;
    const float* xr = g_norm + (size_t)(b * TT) * D;
    float a = 0.f;
    for (int d = lane; d < D; d += 32) a += xr[d] * tw[(size_t)d * NTASK + j];
    for (int o = 16; o; o >>= 1) a += __shfl_xor_sync(0xffffffffu, a, o);
    if (lane == 0) out[b * NTASK + j] = a + tb[j];
}

__global__ void eval_head_kernel(const float* __restrict__ ew, const float* __restrict__ eb,
                                 float* __restrict__ out) {
    int b = blockIdx.x;
    int j = threadIdx.x >> 5, lane = threadIdx.x & 31;
    if (j >= NEVAL) return;
    const float* xr = g_xmean + (size_t)b * D;
    float a = 0.f;
    for (int d = lane; d < D; d += 32) a += xr[d] * ew[(size_t)d * NEVAL + j];
    for (int o = 16; o; o >>= 1) a += __shfl_xor_sync(0xffffffffu, a, o);
    if (lane == 0) out[b * NEVAL + j] = a + eb[j];
}

__global__ void write_aux_kernel(float* __restrict__ out) { out[0] = g_aux[0]; }

// ---------------- host orchestration ----------------
extern "C" void kernel_launch(void* const* d_in, const int* in_sizes, int n_in,
                              void* d_out, int out_size) {
    const int*   ids     = (const int*)d_in[0];
    const float* embed_w = (const float*)d_in[1];
    const float* wq      = (const float*)d_in[2];
    const float* wk      = (const float*)d_in[3];
    const float* wv      = (const float*)d_in[4];
    const float* wo      = (const float*)d_in[5];
    const float* n1w     = (const float*)d_in[6];
    const float* n2w     = (const float*)d_in[7];
    const float* rw      = (const float*)d_in[8];
    const float* wg      = (const float*)d_in[9];
    const float* wu      = (const float*)d_in[10];
    const float* wd      = (const float*)d_in[11];
    const float* nfw     = (const float*)d_in[12];
    const float* lmw     = (const float*)d_in[13];
    const float* tw      = (const float*)d_in[14];
    const float* tb      = (const float*)d_in[15];
    const float* evw     = (const float*)d_in[16];
    const float* evb     = (const float*)d_in[17];
    float* out = (float*)d_out;

    float *p_x, *p_norm, *p_qkv, *p_wqkv, *p_att;
    cudaGetSymbolAddress((void**)&p_x, g_x);
    cudaGetSymbolAddress((void**)&p_norm, g_norm);
    cudaGetSymbolAddress((void**)&p_qkv, g_qkv);
    cudaGetSymbolAddress((void**)&p_wqkv, g_wqkv);
    cudaGetSymbolAddress((void**)&p_att, g_att);

    cudaFuncSetAttribute(attn_kernel, cudaFuncAttributeMaxDynamicSharedMemorySize, ATTN_SMEM);

    embed_kernel<<<NTOK, 256>>>(ids, embed_w);
    zero_aux_kernel<<<1, 1>>>();
    {
        int tot = NLAYER * D * QKVW;
        pack_qkv_kernel<<<(tot + 255) / 256, 256>>>(wq, wk, wv);
    }

    for (int l = 0; l < NLAYER; l++) {
        // ---- attention block ----
        rmsnorm_kernel<<<NTOK, 256>>>(p_x, n1w + (size_t)l * D, p_norm);
        gemm(p_norm, p_wqkv + (size_t)l * D * QKVW, p_qkv, NTOK, QKVW, D);
        {
            int tot = NTOK * (H + KVH) * (HD / 2);
            rope_kernel<<<(tot + 255) / 256, 256>>>();
        }
        {
            dim3 ag(TT / QT, H, BB);
            attn_kernel<<<ag, 256, ATTN_SMEM>>>();
        }
        gemm(p_att, wo + (size_t)l * (H * HD) * D, p_x, NTOK, D, H * HD, /*accum=*/1);

        // ---- MoE block (sparse top-2) ----
        rmsnorm_kernel<<<NTOK, 256>>>(p_x, n2w + (size_t)l * D, p_norm);
        zero_cnt_kernel<<<1, 32>>>();
        router_kernel<<<NTOK, 256>>>(p_norm, rw + (size_t)l * D * NE);
        aux_kernel<<<1, 256>>>();
        {
            dim3 gu(FF / TN, NTOK / TM, NE * 2);
            moe_up_gemm<<<gu, 256>>>(p_norm,
                                     wg + (size_t)l * NE * D * FF,
                                     wu + (size_t)l * NE * D * FF);
            dim3 gd(D / TN, NTOK / TM, NE);
            moe_down_gemm<<<gd, 256>>>(wd + (size_t)l * NE * FF * D);
        }
    }

    // ---- final norm + heads ----
    rmsnorm_kernel<<<NTOK, 256>>>(p_x, nfw, p_norm);
    gemm(p_norm, lmw, out, NTOK, VOCAB, D);

    const size_t LOGITS = (size_t)NTOK * VOCAB;
    task_head_kernel<<<BB, 32 * NTASK>>>(tw, tb, out + LOGITS);
    mean_kernel<<<(BB * D + 255) / 256, 256>>>();
    eval_head_kernel<<<BB, 32 * NEVAL>>>(evw, evb, out + LOGITS + BB * NTASK);
    write_aux_kernel<<<1, 1>>>(out + LOGITS + BB * NTASK + BB * NEVAL);
}

// round 16
// speedup vs baseline: 1.1158x; 1.0539x over previous
#include <cuda_runtime.h>
#include <cuda_bf16.h>
#include <math.h>
#include <stdint.h>

#define NLAYER 4
#define D 1024
#define H 16
#define KVH 4
#define HD 64
#define NE 8
#define KTOP 2
#define FF 512
#define VOCAB 32000
#define BB 2
#define TT 1024
#define NTASK 10
#define NEVAL 5
#define NTOK (BB*TT)
#define EPSV 1e-6f
#define REP (H/KVH)
#define QKVW (H*HD + 2*KVH*HD)   // 1536

#define TM 128
#define TN 128
#define TK 16

#define QT 64
#define APAD 68
#define ATTN_SMEM (3*64*APAD*4)

// ---------------- scratch (device globals; no allocations) ----------------
__device__ float g_x[NTOK*D];
__device__ float g_norm[NTOK*D];
__device__ float g_qkv[NTOK*QKVW];
__device__ float g_wqkv[NLAYER*D*QKVW];
__device__ float g_att[NTOK*D];
__device__ float g_hg[NE*NTOK*FF];
__device__ float g_hu[NE*NTOK*FF];
__device__ float g_probs[NLAYER*NTOK*NE];
__device__ float g_gfull[NTOK*NE];
__device__ int   g_cnt[NE];
__device__ int   g_list[NE*NTOK];
__device__ float g_aux[1];
__device__ float g_xmean[BB*D];

// ---------------- helpers ----------------
// pack two floats to bf16x2: low half = first arg
__device__ __forceinline__ uint32_t packbf(float lo_v, float hi_v) {
    uint32_t r;
    asm("cvt.rn.bf16x2.f32 %0, %1, %2;" : "=r"(r) : "f"(hi_v), "f"(lo_v));
    return r;
}

// split consecutive-k pair (x,y) into hi/lo bf16x2 words
__device__ __forceinline__ void split2(float x, float y, uint32_t& hi, uint32_t& lo) {
    hi = packbf(x, y);
    __nv_bfloat162 h2 = *reinterpret_cast<__nv_bfloat162*>(&hi);
    float rx = x - __bfloat162float(h2.x);
    float ry = y - __bfloat162float(h2.y);
    lo = packbf(rx, ry);
}

__device__ __forceinline__ void mma_bf16(float (&c)[4], uint32_t a0, uint32_t a1,
                                         uint32_t a2, uint32_t a3, uint32_t b0, uint32_t b1) {
    asm volatile(
        "mma.sync.aligned.m16n8k16.row.col.f32.bf16.bf16.f32 "
        "{%0,%1,%2,%3}, {%4,%5,%6,%7}, {%8,%9}, {%0,%1,%2,%3};"
        : "+f"(c[0]), "+f"(c[1]), "+f"(c[2]), "+f"(c[3])
        : "r"(a0), "r"(a1), "r"(a2), "r"(a3), "r"(b0), "r"(b1));
}

__device__ __forceinline__ float siluf(float g) { return g / (1.f + expf(-g)); }

__device__ __forceinline__ float4 silu_mul4(float4 g, float4 u) {
    float4 r;
    r.x = siluf(g.x) * u.x;
    r.y = siluf(g.y) * u.y;
    r.z = siluf(g.z) * u.z;
    r.w = siluf(g.w) * u.w;
    return r;
}

#define GEMM_SMEM_DECL                                \
    __shared__ uint32_t Ahi[8][TM + 8];               \
    __shared__ uint32_t Alo[8][TM + 8];               \
    __shared__ uint32_t Bhi[8][TN + 8];               \
    __shared__ uint32_t Blo[8][TN + 8];

// store A float4 (4 consecutive k) as two hi/lo bf16x2 pairs, transposed
#define STORE_A(pa, acol, r)                                                  \
    do {                                                                       \
        split2(pa.x, pa.y, Ahi[(acol) >> 1][r], Alo[(acol) >> 1][r]);          \
        split2(pa.z, pa.w, Ahi[((acol) >> 1) + 1][r], Alo[((acol) >> 1) + 1][r]);\
    } while (0)

// store B k-pair rows (pb0 = row 2kp, pb1 = row 2kp+1) packed by k
#define STORE_B(pb0, pb1, kp, ncol)                                           \
    do {                                                                       \
        split2(pb0.x, pb1.x, Bhi[kp][(ncol) + 0], Blo[kp][(ncol) + 0]);        \
        split2(pb0.y, pb1.y, Bhi[kp][(ncol) + 1], Blo[kp][(ncol) + 1]);        \
        split2(pb0.z, pb1.z, Bhi[kp][(ncol) + 2], Blo[kp][(ncol) + 2]);        \
        split2(pb0.w, pb1.w, Bhi[kp][(ncol) + 3], Blo[kp][(ncol) + 3]);        \
    } while (0)

// one 16-k step of 3-product bf16 emulated-fp32 mma
#define MMA_STEP16(mb, nb, lane, c)                                           \
    do {                                                                       \
        int kq = (lane) & 3;                                                   \
        int mrw = (lane) >> 2;                                                 \
        uint32_t ah[4][4], al[4][4], bh[4][2], bl[4][2];                       \
        _Pragma("unroll") for (int mt = 0; mt < 4; mt++) {                     \
            int m = (mb) + mt * 16 + mrw;                                      \
            ah[mt][0] = Ahi[kq][m];     ah[mt][1] = Ahi[kq][m + 8];            \
            ah[mt][2] = Ahi[kq + 4][m]; ah[mt][3] = Ahi[kq + 4][m + 8];        \
            al[mt][0] = Alo[kq][m];     al[mt][1] = Alo[kq][m + 8];            \
            al[mt][2] = Alo[kq + 4][m]; al[mt][3] = Alo[kq + 4][m + 8];        \
        }                                                                      \
        _Pragma("unroll") for (int nt = 0; nt < 4; nt++) {                     \
            int n = (nb) + nt * 8 + mrw;                                       \
            bh[nt][0] = Bhi[kq][n]; bh[nt][1] = Bhi[kq + 4][n];                \
            bl[nt][0] = Blo[kq][n]; bl[nt][1] = Blo[kq + 4][n];                \
        }                                                                      \
        _Pragma("unroll") for (int mt = 0; mt < 4; mt++)                       \
            _Pragma("unroll") for (int nt = 0; nt < 4; nt++) {                 \
                mma_bf16(c[mt][nt], ah[mt][0], ah[mt][1], ah[mt][2],           \
                         ah[mt][3], bl[nt][0], bl[nt][1]);                     \
                mma_bf16(c[mt][nt], al[mt][0], al[mt][1], al[mt][2],           \
                         al[mt][3], bh[nt][0], bh[nt][1]);                     \
                mma_bf16(c[mt][nt], ah[mt][0], ah[mt][1], ah[mt][2],           \
                         ah[mt][3], bh[nt][0], bh[nt][1]);                     \
            }                                                                  \
    } while (0)

// ---------------- embedding gather ----------------
__global__ void embed_kernel(const int* __restrict__ ids, const float* __restrict__ ew) {
    int n = blockIdx.x;
    int id = ids[n];
    const float* src = ew + (size_t)id * D;
    float* dst = g_x + (size_t)n * D;
    for (int d = threadIdx.x; d < D; d += blockDim.x) dst[d] = src[d];
}

// ---------------- rmsnorm ----------------
__global__ void rmsnorm_kernel(const float* __restrict__ x, const float* __restrict__ w,
                               float* __restrict__ out) {
    int n = blockIdx.x;
    const float* xr = x + (size_t)n * D;
    float s = 0.f;
    for (int d = threadIdx.x; d < D; d += blockDim.x) { float v = xr[d]; s += v * v; }
    for (int o = 16; o; o >>= 1) s += __shfl_xor_sync(0xffffffffu, s, o);
    __shared__ float rb[8];
    if ((threadIdx.x & 31) == 0) rb[threadIdx.x >> 5] = s;
    __syncthreads();
    __shared__ float srms;
    if (threadIdx.x == 0) {
        float t = 0.f;
        for (int i = 0; i < 8; i++) t += rb[i];
        srms = rsqrtf(t / D + EPSV);
    }
    __syncthreads();
    float rms = srms;
    float* o2 = out + (size_t)n * D;
    for (int d = threadIdx.x; d < D; d += blockDim.x) o2[d] = w[d] * xr[d] * rms;
}

// ================= bf16x3 tensor-core GEMM (dense, single buffer — R6) =============
// C[M,N] (+)= A[M,K] @ B[K,N].  N%128==0, K%16==0.
// mswap=0: grid (N-blocks, M-blocks).  mswap=1: grid (M-blocks, N-blocks) —
// M-blocks fastest, so concurrent CTAs share B tiles in L2 (used for lm_head,
// whose B exceeds L2 capacity).
__global__ __launch_bounds__(256) void gemm_bf16(
    const float* __restrict__ A, const float* __restrict__ B, float* __restrict__ C,
    int M, int N, int K, int accum, int mswap) {
    GEMM_SMEM_DECL
    int tid = threadIdx.x;
    int row0 = (mswap ? blockIdx.x : blockIdx.y) * TM;
    int col0 = (mswap ? blockIdx.y : blockIdx.x) * TN;
    if (row0 >= M) return;
    int lane = tid & 31, w = tid >> 5;
    int mb = (w & 1) * 64, nb = (w >> 1) * 32;
    int arow = tid >> 2, acol = (tid & 3) << 2;
    int kp = tid >> 5, ncol = (tid & 31) << 2;

    const float* Aptr[2]; bool av[2];
#pragma unroll
    for (int i = 0; i < 2; i++) {
        int r = row0 + arow + i * 64;
        av[i] = (r < M);
        Aptr[i] = A + (size_t)(av[i] ? r : (M - 1)) * K + acol;
    }
    const float* Bp0 = B + (size_t)(2 * kp) * N + col0 + ncol;
    const float* Bp1 = Bp0 + N;

    float4 pa[2], pb0, pb1;
#pragma unroll
    for (int i = 0; i < 2; i++)
        pa[i] = av[i] ? *(const float4*)(Aptr[i]) : make_float4(0.f, 0.f, 0.f, 0.f);
    pb0 = *(const float4*)(Bp0);
    pb1 = *(const float4*)(Bp1);

    float c[4][4][4] = {};
    for (int k0 = 0; k0 < K; k0 += TK) {
#pragma unroll
        for (int i = 0; i < 2; i++) STORE_A(pa[i], acol, arow + i * 64);
        STORE_B(pb0, pb1, kp, ncol);
        __syncthreads();
        if (k0 + TK < K) {
#pragma unroll
            for (int i = 0; i < 2; i++)
                pa[i] = av[i] ? *(const float4*)(Aptr[i] + k0 + TK) : make_float4(0.f, 0.f, 0.f, 0.f);
            pb0 = *(const float4*)(Bp0 + (size_t)(k0 + TK) * N);
            pb1 = *(const float4*)(Bp1 + (size_t)(k0 + TK) * N);
        }
        MMA_STEP16(mb, nb, lane, c);
        __syncthreads();
    }
#pragma unroll
    for (int mt = 0; mt < 4; mt++) {
        int rt = row0 + mb + mt * 16 + (lane >> 2);
#pragma unroll
        for (int nt = 0; nt < 4; nt++) {
            int cc = col0 + nb + nt * 8 + ((lane & 3) << 1);
            if (rt < M) {
                float2* p = (float2*)&C[(size_t)rt * N + cc];
                float2 v = make_float2(c[mt][nt][0], c[mt][nt][1]);
                if (accum) { float2 o = *p; v.x += o.x; v.y += o.y; }
                *p = v;
            }
            if (rt + 8 < M) {
                float2* p = (float2*)&C[(size_t)(rt + 8) * N + cc];
                float2 v = make_float2(c[mt][nt][2], c[mt][nt][3]);
                if (accum) { float2 o = *p; v.x += o.x; v.y += o.y; }
                *p = v;
            }
        }
    }
}

static inline void gemm(const float* A, const float* B, float* C, int M, int N, int K,
                        int accum = 0) {
    dim3 grid(N / TN, (M + TM - 1) / TM);
    gemm_bf16<<<grid, 256>>>(A, B, C, M, N, K, accum, 0);
}

// M-major launch: concurrent CTAs share B tiles (for B bigger than L2)
static inline void gemm_lm(const float* A, const float* B, float* C, int M, int N, int K) {
    dim3 grid((M + TM - 1) / TM, N / TN);
    gemm_bf16<<<grid, 256>>>(A, B, C, M, N, K, 0, 1);
}

// ================= MoE up/gate GEMM (gathered A, bf16x3 — R6) =================
__global__ __launch_bounds__(256) void moe_up_gemm(
    const float* __restrict__ Xn, const float* __restrict__ Wg, const float* __restrict__ Wu) {
    int z = blockIdx.z;
    int e = z >> 1, u = z & 1;
    int cnt = g_cnt[e];
    int row0 = blockIdx.y * TM;
    if (row0 >= cnt) return;
    GEMM_SMEM_DECL
    int tid = threadIdx.x;
    int col0 = blockIdx.x * TN;
    int lane = tid & 31, w = tid >> 5;
    int mb = (w & 1) * 64, nb = (w >> 1) * 32;
    int arow = tid >> 2, acol = (tid & 3) << 2;
    int kp = tid >> 5, ncol = (tid & 31) << 2;
    const int* list = g_list + e * NTOK;
    const float* B = (u ? Wu : Wg) + (size_t)e * D * FF;
    float* C = (u ? g_hu : g_hg) + (size_t)e * NTOK * FF;

    const float* Aptr[2]; bool av[2];
#pragma unroll
    for (int i = 0; i < 2; i++) {
        int r = row0 + arow + i * 64;
        av[i] = (r < cnt);
        Aptr[i] = Xn + (size_t)list[av[i] ? r : (cnt - 1)] * D + acol;
    }
    const float* Bp0 = B + (size_t)(2 * kp) * FF + col0 + ncol;
    const float* Bp1 = Bp0 + FF;

    float4 pa[2], pb0, pb1;
#pragma unroll
    for (int i = 0; i < 2; i++)
        pa[i] = av[i] ? *(const float4*)(Aptr[i]) : make_float4(0.f, 0.f, 0.f, 0.f);
    pb0 = *(const float4*)(Bp0);
    pb1 = *(const float4*)(Bp1);

    float c[4][4][4] = {};
    for (int k0 = 0; k0 < D; k0 += TK) {
#pragma unroll
        for (int i = 0; i < 2; i++) STORE_A(pa[i], acol, arow + i * 64);
        STORE_B(pb0, pb1, kp, ncol);
        __syncthreads();
        if (k0 + TK < D) {
#pragma unroll
            for (int i = 0; i < 2; i++)
                pa[i] = av[i] ? *(const float4*)(Aptr[i] + k0 + TK) : make_float4(0.f, 0.f, 0.f, 0.f);
            pb0 = *(const float4*)(Bp0 + (size_t)(k0 + TK) * FF);
            pb1 = *(const float4*)(Bp1 + (size_t)(k0 + TK) * FF);
        }
        MMA_STEP16(mb, nb, lane, c);
        __syncthreads();
    }
#pragma unroll
    for (int mt = 0; mt < 4; mt++) {
        int rt = row0 + mb + mt * 16 + (lane >> 2);
#pragma unroll
        for (int nt = 0; nt < 4; nt++) {
            int cc = col0 + nb + nt * 8 + ((lane & 3) << 1);
            if (rt < cnt)
                *(float2*)&C[(size_t)rt * FF + cc] = make_float2(c[mt][nt][0], c[mt][nt][1]);
            if (rt + 8 < cnt)
                *(float2*)&C[(size_t)(rt + 8) * FF + cc] = make_float2(c[mt][nt][2], c[mt][nt][3]);
        }
    }
}

// ========== MoE down GEMM (silu-fused A, gated scatter-add, bf16x3 — R6) ==========
__global__ __launch_bounds__(256) void moe_down_gemm(const float* __restrict__ Wd) {
    int e = blockIdx.z;
    int cnt = g_cnt[e];
    int row0 = blockIdx.y * TM;
    if (row0 >= cnt) return;
    GEMM_SMEM_DECL
    int tid = threadIdx.x;
    int col0 = blockIdx.x * TN;
    int lane = tid & 31, w = tid >> 5;
    int mb = (w & 1) * 64, nb = (w >> 1) * 32;
    int arow = tid >> 2, acol = (tid & 3) << 2;
    int kp = tid >> 5, ncol = (tid & 31) << 2;
    const int* list = g_list + e * NTOK;
    const float* hgB = g_hg + (size_t)e * NTOK * FF;
    const float* huB = g_hu + (size_t)e * NTOK * FF;
    const float* B = Wd + (size_t)e * FF * D;

    const float* gp[2]; const float* up[2]; bool av[2];
#pragma unroll
    for (int i = 0; i < 2; i++) {
        int r = row0 + arow + i * 64;
        av[i] = (r < cnt);
        int rc = av[i] ? r : (cnt - 1);
        gp[i] = hgB + (size_t)rc * FF + acol;
        up[i] = huB + (size_t)rc * FF + acol;
    }
    const float* Bp0 = B + (size_t)(2 * kp) * D + col0 + ncol;
    const float* Bp1 = Bp0 + D;

    float4 pa[2], pb0, pb1;
#pragma unroll
    for (int i = 0; i < 2; i++)
        pa[i] = av[i] ? silu_mul4(*(const float4*)gp[i], *(const float4*)up[i])
                      : make_float4(0.f, 0.f, 0.f, 0.f);
    pb0 = *(const float4*)(Bp0);
    pb1 = *(const float4*)(Bp1);

    float c[4][4][4] = {};
    for (int k0 = 0; k0 < FF; k0 += TK) {
#pragma unroll
        for (int i = 0; i < 2; i++) STORE_A(pa[i], acol, arow + i * 64);
        STORE_B(pb0, pb1, kp, ncol);
        __syncthreads();
        if (k0 + TK < FF) {
#pragma unroll
            for (int i = 0; i < 2; i++)
                pa[i] = av[i] ? silu_mul4(*(const float4*)(gp[i] + k0 + TK),
                                          *(const float4*)(up[i] + k0 + TK))
                              : make_float4(0.f, 0.f, 0.f, 0.f);
            pb0 = *(const float4*)(Bp0 + (size_t)(k0 + TK) * D);
            pb1 = *(const float4*)(Bp1 + (size_t)(k0 + TK) * D);
        }
        MMA_STEP16(mb, nb, lane, c);
        __syncthreads();
    }
#pragma unroll
    for (int mt = 0; mt < 4; mt++) {
        int rt = row0 + mb + mt * 16 + (lane >> 2);
#pragma unroll
        for (int half = 0; half < 2; half++) {
            int r = rt + half * 8;
            if (r >= cnt) continue;
            int tok = list[r];
            float gate = g_gfull[tok * NE + e];
#pragma unroll
            for (int nt = 0; nt < 4; nt++) {
                int cc = col0 + nb + nt * 8 + ((lane & 3) << 1);
                float* xp = g_x + (size_t)tok * D + cc;
                atomicAdd(xp + 0, gate * c[mt][nt][half * 2 + 0]);
                atomicAdd(xp + 1, gate * c[mt][nt][half * 2 + 1]);
            }
        }
    }
}

// ---------------- QKV weight pack (all layers at once) ----------------
__global__ void pack_qkv_kernel(const float* __restrict__ wq, const float* __restrict__ wk,
                                const float* __restrict__ wv) {
    int idx = blockIdx.x * blockDim.x + threadIdx.x;
    if (idx >= NLAYER * D * QKVW) return;
    int l = idx / (D * QKVW);
    int rest = idx - l * (D * QKVW);
    int d = rest / QKVW, c = rest % QKVW;
    float v;
    if (c < H * HD) v = wq[((size_t)l * D + d) * (H * HD) + c];
    else if (c < H * HD + KVH * HD) v = wk[((size_t)l * D + d) * (KVH * HD) + (c - H * HD)];
    else v = wv[((size_t)l * D + d) * (KVH * HD) + (c - H * HD - KVH * HD)];
    g_wqkv[idx] = v;
}

// ---------------- RoPE over packed qkv (q and k heads in one launch) ----------------
__global__ void rope_kernel() {
    int idx = blockIdx.x * blockDim.x + threadIdx.x;
    const int total = NTOK * (H + KVH) * (HD / 2);
    if (idx >= total) return;
    int i = idx % (HD / 2);
    int rest = idx / (HD / 2);
    int hh = rest % (H + KVH);
    int n = rest / (H + KVH);
    int t = n % TT;
    int off = (hh < H) ? hh * HD : H * HD + (hh - H) * HD;
    float inv = exp2f(-((float)(2 * i) / (float)HD) * 19.9315685693241741f);
    float fr = (float)t * inv;
    float c, s;
    sincosf(fr, &s, &c);
    float* p = g_qkv + (size_t)n * QKVW + off + 2 * i;
    float x1 = p[0], x2 = p[1];
    p[0] = x1 * c - x2 * s;
    p[1] = x1 * s + x2 * c;
}

// ---------------- tiled causal attention (flash-style, fp32 — R6) ----------------
__global__ __launch_bounds__(256) void attn_kernel() {
    extern __shared__ float sm[];
    float* Qs = sm;
    float* Ks = sm + 64 * APAD;
    float* Vs = sm + 2 * 64 * APAD;
    int q0 = (gridDim.x - 1 - blockIdx.x) * QT;
    int h = blockIdx.y, b = blockIdx.z;
    int kvh = h / REP;
    int tid = threadIdx.x;
    int tx = tid & 15, ty = tid >> 4;
    const size_t qoff = (size_t)h * HD;
    const size_t koff = (size_t)(H * HD) + kvh * HD;
    const size_t voff = (size_t)(H * HD + KVH * HD) + kvh * HD;

    {
        int qi = tid & 63, c0 = (tid >> 6) * 16;
        const float* qp = g_qkv + (size_t)(b * TT + q0 + qi) * QKVW + qoff + c0;
#pragma unroll
        for (int t = 0; t < 4; t++) {
            float4 v = *(const float4*)(qp + 4 * t);
            Qs[(c0 + 4 * t + 0) * APAD + qi] = v.x;
            Qs[(c0 + 4 * t + 1) * APAD + qi] = v.y;
            Qs[(c0 + 4 * t + 2) * APAD + qi] = v.z;
            Qs[(c0 + 4 * t + 3) * APAD + qi] = v.w;
        }
    }

    float O[4][4] = {};
    float mrow[4], lrow[4];
#pragma unroll
    for (int i = 0; i < 4; i++) { mrow[i] = -1e30f; lrow[i] = 0.f; }

    int ntiles = q0 / QT + 1;
    for (int t0 = 0; t0 < ntiles; t0++) {
        int k0 = t0 * QT;
        __syncthreads();
        {
            int kj = tid & 63, c0 = (tid >> 6) * 16;
            const float* kpp = g_qkv + (size_t)(b * TT + k0 + kj) * QKVW + koff + c0;
            const float* vpp = g_qkv + (size_t)(b * TT + k0 + kj) * QKVW + voff + c0;
#pragma unroll
            for (int t = 0; t < 4; t++) {
                float4 v = *(const float4*)(kpp + 4 * t);
                Ks[(c0 + 4 * t + 0) * APAD + kj] = v.x;
                Ks[(c0 + 4 * t + 1) * APAD + kj] = v.y;
                Ks[(c0 + 4 * t + 2) * APAD + kj] = v.z;
                Ks[(c0 + 4 * t + 3) * APAD + kj] = v.w;
                *(float4*)&Vs[kj * APAD + c0 + 4 * t] = *(const float4*)(vpp + 4 * t);
            }
        }
        __syncthreads();
        float s[4][4] = {};
        for (int d = 0; d < HD; d++) {
            float4 a = *(const float4*)&Qs[d * APAD + ty * 4];
            float4 bq = *(const float4*)&Ks[d * APAD + tx * 4];
            const float av[4] = {a.x, a.y, a.z, a.w};
            const float bv[4] = {bq.x, bq.y, bq.z, bq.w};
#pragma unroll
            for (int i = 0; i < 4; i++)
#pragma unroll
                for (int j = 0; j < 4; j++) s[i][j] += av[i] * bv[j];
        }
#pragma unroll
        for (int i = 0; i < 4; i++)
#pragma unroll
            for (int j = 0; j < 4; j++) s[i][j] *= 0.125f;
        if (k0 == q0) {
#pragma unroll
            for (int i = 0; i < 4; i++)
#pragma unroll
                for (int j = 0; j < 4; j++)
                    if (k0 + tx * 4 + j > q0 + ty * 4 + i) s[i][j] = -1e30f;
        }
        __syncthreads();
#pragma unroll
        for (int i = 0; i < 4; i++) {
            float tm = fmaxf(fmaxf(s[i][0], s[i][1]), fmaxf(s[i][2], s[i][3]));
#pragma unroll
            for (int o = 8; o; o >>= 1) tm = fmaxf(tm, __shfl_xor_sync(0xffffffffu, tm, o));
            float mn = fmaxf(mrow[i], tm);
            float sc = expf(mrow[i] - mn);
            float p0 = expf(s[i][0] - mn), p1 = expf(s[i][1] - mn);
            float p2 = expf(s[i][2] - mn), p3 = expf(s[i][3] - mn);
            float rs = p0 + p1 + p2 + p3;
#pragma unroll
            for (int o = 8; o; o >>= 1) rs += __shfl_xor_sync(0xffffffffu, rs, o);
            lrow[i] = lrow[i] * sc + rs;
            mrow[i] = mn;
#pragma unroll
            for (int j = 0; j < 4; j++) O[i][j] *= sc;
            *(float4*)&Ks[(ty * 4 + i) * APAD + tx * 4] = make_float4(p0, p1, p2, p3);
        }
        __syncthreads();
        for (int kk = 0; kk < QT; kk++) {
            float4 vv = *(const float4*)&Vs[kk * APAD + tx * 4];
            const float vb[4] = {vv.x, vv.y, vv.z, vv.w};
            float a0 = Ks[(ty * 4 + 0) * APAD + kk];
            float a1 = Ks[(ty * 4 + 1) * APAD + kk];
            float a2 = Ks[(ty * 4 + 2) * APAD + kk];
            float a3 = Ks[(ty * 4 + 3) * APAD + kk];
#pragma unroll
            for (int j = 0; j < 4; j++) {
                O[0][j] += a0 * vb[j];
                O[1][j] += a1 * vb[j];
                O[2][j] += a2 * vb[j];
                O[3][j] += a3 * vb[j];
            }
        }
    }
#pragma unroll
    for (int i = 0; i < 4; i++) {
        float inv = 1.f / lrow[i];
        float4 o = make_float4(O[i][0] * inv, O[i][1] * inv, O[i][2] * inv, O[i][3] * inv);
        *(float4*)&g_att[(size_t)(b * TT + q0 + ty * 4 + i) * D + h * HD + tx * 4] = o;
    }
}

// ------- router: softmax + top-2 gates + expert list append (per-layer probs) ------
__global__ void router_kernel(const float* __restrict__ xn, const float* __restrict__ rw,
                              float* __restrict__ probs_out) {
    int n = blockIdx.x;
    int warp = threadIdx.x >> 5, lane = threadIdx.x & 31;
    __shared__ float sdot[NE];
    const float* xr = xn + (size_t)n * D;
    float acc = 0.f;
    for (int d = lane; d < D; d += 32) acc += xr[d] * rw[(size_t)d * NE + warp];
    for (int o = 16; o; o >>= 1) acc += __shfl_xor_sync(0xffffffffu, acc, o);
    if (lane == 0) sdot[warp] = acc;
    __syncthreads();
    if (threadIdx.x == 0) {
        float m = -1e30f;
        for (int e = 0; e < NE; e++) m = fmaxf(m, sdot[e]);
        float p[NE], s = 0.f;
        for (int e = 0; e < NE; e++) { p[e] = expf(sdot[e] - m); s += p[e]; }
        for (int e = 0; e < NE; e++) p[e] /= s;
        int i1 = 0;
        for (int e = 1; e < NE; e++) if (p[e] > p[i1]) i1 = e;
        int i2 = -1;
        for (int e = 0; e < NE; e++) {
            if (e == i1) continue;
            if (i2 < 0 || p[e] > p[i2]) i2 = e;
        }
        float gs = p[i1] + p[i2];
        for (int e = 0; e < NE; e++) {
            probs_out[n * NE + e] = p[e];
            g_gfull[n * NE + e] = (e == i1) ? p[i1] / gs : (e == i2 ? p[i2] / gs : 0.f);
        }
        int pos1 = atomicAdd(&g_cnt[i1], 1);
        g_list[i1 * NTOK + pos1] = n;
        int pos2 = atomicAdd(&g_cnt[i2], 1);
        g_list[i2 * NTOK + pos2] = n;
    }
}

// ---------------- expert count zero ----------------
__global__ void zero_cnt_kernel() {
    if (threadIdx.x < NE) g_cnt[threadIdx.x] = 0;
}

// --------- aux loss: one block per layer, end of model (recomputes top-2) ---------
__global__ void aux_all_kernel() {
    int l = blockIdx.x;
    const float* probs = g_probs + (size_t)l * NTOK * NE;
    __shared__ float sme[NE], sce[NE];
    int tid = threadIdx.x;
    if (tid < NE) { sme[tid] = 0.f; sce[tid] = 0.f; }
    __syncthreads();
    float me[NE] = {}, ce[NE] = {};
    for (int n = tid; n < NTOK; n += blockDim.x) {
        float p[NE];
        for (int e = 0; e < NE; e++) { p[e] = probs[n * NE + e]; me[e] += p[e]; }
        int i1 = 0;
        for (int e = 1; e < NE; e++) if (p[e] > p[i1]) i1 = e;
        int i2 = -1;
        for (int e = 0; e < NE; e++) {
            if (e == i1) continue;
            if (i2 < 0 || p[e] > p[i2]) i2 = e;
        }
        float gs = p[i1] + p[i2];
        // mirror reference: count only strictly-positive gates
        if (p[i1] / gs > 0.f) ce[i1] += 1.f;
        if (p[i2] / gs > 0.f) ce[i2] += 1.f;
    }
    for (int e = 0; e < NE; e++) { atomicAdd(&sme[e], me[e]); atomicAdd(&sce[e], ce[e]); }
    __syncthreads();
    if (tid == 0) {
        float a = 0.f;
        for (int e = 0; e < NE; e++)
            a += (sme[e] / NTOK) * (sce[e] / (float)(NTOK * KTOP));
        atomicAdd(&g_aux[0], NE * a);
    }
}

__global__ void zero_aux_kernel() { g_aux[0] = 0.f; }

// ---------------- final heads ----------------
__global__ void mean_kernel() {
    int idx = blockIdx.x * blockDim.x + threadIdx.x;
    if (idx >= BB * D) return;
    int b = idx / D, d = idx % D;
    float s = 0.f;
    for (int t = 0; t < TT; t++) s += g_norm[(size_t)(b * TT + t) * D + d];
    g_xmean[idx] = s / TT;
}

__global__ void task_head_kernel(const float* __restrict__ tw, const float* __restrict__ tb,
                                 float* __restrict__ out) {
    int b = blockIdx.x;
    int j = threadIdx.x >> 5, lane = threadIdx.x & 31;
    if (j >= NTASK) return;
    const float* xr = g_norm + (size_t)(b * TT) * D;
    float a = 0.f;
    for (int d = lane; d < D; d += 32) a += xr[d] * tw[(size_t)d * NTASK + j];
    for (int o = 16; o; o >>= 1) a += __shfl_xor_sync(0xffffffffu, a, o);
    if (lane == 0) out[b * NTASK + j] = a + tb[j];
}

__global__ void eval_head_kernel(const float* __restrict__ ew, const float* __restrict__ eb,
                                 float* __restrict__ out) {
    int b = blockIdx.x;
    int j = threadIdx.x >> 5, lane = threadIdx.x & 31;
    if (j >= NEVAL) return;
    const float* xr = g_xmean + (size_t)b * D;
    float a = 0.f;
    for (int d = lane; d < D; d += 32) a += xr[d] * ew[(size_t)d * NEVAL + j];
    for (int o = 16; o; o >>= 1) a += __shfl_xor_sync(0xffffffffu, a, o);
    if (lane == 0) out[b * NEVAL + j] = a + eb[j];
}

__global__ void write_aux_kernel(float* __restrict__ out) { out[0] = g_aux[0]; }

// ---------------- host orchestration ----------------
extern "C" void kernel_launch(void* const* d_in, const int* in_sizes, int n_in,
                              void* d_out, int out_size) {
    const int*   ids     = (const int*)d_in[0];
    const float* embed_w = (const float*)d_in[1];
    const float* wq      = (const float*)d_in[2];
    const float* wk      = (const float*)d_in[3];
    const float* wv      = (const float*)d_in[4];
    const float* wo      = (const float*)d_in[5];
    const float* n1w     = (const float*)d_in[6];
    const float* n2w     = (const float*)d_in[7];
    const float* rw      = (const float*)d_in[8];
    const float* wg      = (const float*)d_in[9];
    const float* wu      = (const float*)d_in[10];
    const float* wd      = (const float*)d_in[11];
    const float* nfw     = (const float*)d_in[12];
    const float* lmw     = (const float*)d_in[13];
    const float* tw      = (const float*)d_in[14];
    const float* tb      = (const float*)d_in[15];
    const float* evw     = (const float*)d_in[16];
    const float* evb     = (const float*)d_in[17];
    float* out = (float*)d_out;

    float *p_x, *p_norm, *p_qkv, *p_wqkv, *p_att, *p_probs;
    cudaGetSymbolAddress((void**)&p_x, g_x);
    cudaGetSymbolAddress((void**)&p_norm, g_norm);
    cudaGetSymbolAddress((void**)&p_qkv, g_qkv);
    cudaGetSymbolAddress((void**)&p_wqkv, g_wqkv);
    cudaGetSymbolAddress((void**)&p_att, g_att);
    cudaGetSymbolAddress((void**)&p_probs, g_probs);

    cudaFuncSetAttribute(attn_kernel, cudaFuncAttributeMaxDynamicSharedMemorySize, ATTN_SMEM);

    embed_kernel<<<NTOK, 256>>>(ids, embed_w);
    zero_aux_kernel<<<1, 1>>>();
    {
        int tot = NLAYER * D * QKVW;
        pack_qkv_kernel<<<(tot + 255) / 256, 256>>>(wq, wk, wv);
    }

    for (int l = 0; l < NLAYER; l++) {
        // ---- attention block ----
        rmsnorm_kernel<<<NTOK, 256>>>(p_x, n1w + (size_t)l * D, p_norm);
        gemm(p_norm, p_wqkv + (size_t)l * D * QKVW, p_qkv, NTOK, QKVW, D);
        {
            int tot = NTOK * (H + KVH) * (HD / 2);
            rope_kernel<<<(tot + 255) / 256, 256>>>();
        }
        {
            dim3 ag(TT / QT, H, BB);
            attn_kernel<<<ag, 256, ATTN_SMEM>>>();
        }
        gemm(p_att, wo + (size_t)l * (H * HD) * D, p_x, NTOK, D, H * HD, /*accum=*/1);

        // ---- MoE block (sparse top-2) ----
        rmsnorm_kernel<<<NTOK, 256>>>(p_x, n2w + (size_t)l * D, p_norm);
        zero_cnt_kernel<<<1, 32>>>();
        router_kernel<<<NTOK, 256>>>(p_norm, rw + (size_t)l * D * NE,
                                     p_probs + (size_t)l * NTOK * NE);
        {
            dim3 gu(FF / TN, NTOK / TM, NE * 2);
            moe_up_gemm<<<gu, 256>>>(p_norm,
                                     wg + (size_t)l * NE * D * FF,
                                     wu + (size_t)l * NE * D * FF);
            dim3 gd(D / TN, NTOK / TM, NE);
            moe_down_gemm<<<gd, 256>>>(wd + (size_t)l * NE * FF * D);
        }
    }

    // ---- final norm + heads ----
    rmsnorm_kernel<<<NTOK, 256>>>(p_x, nfw, p_norm);
    gemm_lm(p_norm, lmw, out, NTOK, VOCAB, D);   // M-major grid: B tiles shared in L2

    const size_t LOGITS = (size_t)NTOK * VOCAB;
    task_head_kernel<<<BB, 32 * NTASK>>>(tw, tb, out + LOGITS);
    mean_kernel<<<(BB * D + 255) / 256, 256>>>();
    eval_head_kernel<<<BB, 32 * NEVAL>>>(evw, evb, out + LOGITS + BB * NTASK);
    aux_all_kernel<<<NLAYER, 256>>>();
    write_aux_kernel<<<1, 1>>>(out + LOGITS + BB * NTASK + BB * NEVAL);
}